// round 1
// baseline (speedup 1.0000x reference)
#include <cuda_runtime.h>
#include <math.h>

// ---------------- problem constants ----------------
#define Bn    128
#define TU    256
#define TBt   128
#define TPt   64
#define Hd    512
#define Ed    512
#define Vd    3000
#define VOOVd 3400
#define PTRd  32
#define XD    2080   // E + 3H + PTR
#define G3H   1536
#define NEGV  (-1e20f)

// ---------------- scratch layout (floats) ----------------
constexpr size_t OFF_W2T  = 0;                           // 512x512  (k,j) = attn_W[j, H+k]
constexpr size_t OFF_WCT  = OFF_W2T  + 512*512;          // 512x512  Wcopy^T
constexpr size_t OFF_WGT  = OFF_WCT  + 512*512;          // 512x3000 Wgen^T
constexpr size_t OFF_U    = OFF_WGT  + (size_t)512*3000; // B x H    u = W1@h0 + attn_b
constexpr size_t OFF_GH   = OFF_U    + (size_t)Bn*Hd;    // B x 3H
constexpr size_t OFF_EU   = OFF_GH   + (size_t)Bn*G3H;   // B*TU x H
constexpr size_t OFF_EB   = OFF_EU   + (size_t)Bn*TU*Hd; // B*TB x H
constexpr size_t OFF_EP   = OFF_EB   + (size_t)Bn*TBt*Hd;// B*TP x H
constexpr size_t OFF_BCP  = OFF_EP   + (size_t)Bn*TPt*Hd;// B*TB x H (copy pre-act)
constexpr size_t OFF_SU   = OFF_BCP  + (size_t)Bn*TBt*Hd;
constexpr size_t OFF_SB   = OFF_SU   + (size_t)Bn*TU;
constexpr size_t OFF_SP   = OFF_SB   + (size_t)Bn*TBt;
constexpr size_t OFF_X    = OFF_SP   + (size_t)Bn*TPt;   // B x 2080
constexpr size_t OFF_HNEW = OFF_X    + (size_t)Bn*XD;
constexpr size_t OFF_GEN  = OFF_HNEW + (size_t)Bn*Hd;    // B x V (pre-bias)
constexpr size_t OFF_CPR  = OFF_GEN  + (size_t)Bn*Vd;    // B x TB
constexpr size_t TOT_SCRATCH = OFF_CPR + (size_t)Bn*TBt;

__device__ float g_scratch[TOT_SCRATCH];

__device__ __forceinline__ float warp_sum(float v) {
    #pragma unroll
    for (int s = 16; s; s >>= 1) v += __shfl_down_sync(0xffffffffu, v, s);
    return v;
}
__device__ __forceinline__ float sigmoidf_(float x) { return 1.0f / (1.0f + expf(-x)); }

// ---------------- transpose: outp[k*rows + j] = in[j*instride + coloff + k] ----------------
__global__ void transpose_k(const float* __restrict__ in, float* __restrict__ outp,
                            int rows, int cols, int instride, int coloff) {
    int idx = blockIdx.x * 256 + threadIdx.x;
    if (idx >= rows * cols) return;
    int k = idx / rows, j = idx % rows;
    outp[idx] = in[(size_t)j * instride + coloff + k];
}

// ---------------- per-batch prep: u = W1@h0 + attn_b, gh = Whh@h0 + bhh ----------------
__global__ void prep_k(const float* __restrict__ h0, const float* __restrict__ attn_W,
                       const float* __restrict__ attn_b, const float* __restrict__ Whh,
                       const float* __restrict__ bhh, float* __restrict__ u, float* __restrict__ gh) {
    int b = blockIdx.x;
    __shared__ float sh[Hd];
    for (int i = threadIdx.x; i < Hd; i += 256) sh[i] = h0[(size_t)b * Hd + i];
    __syncthreads();
    int warp = threadIdx.x >> 5, lane = threadIdx.x & 31;
    for (int o = warp; o < Hd + G3H; o += 8) {
        const float* wrow; float bias;
        if (o < Hd) { wrow = attn_W + (size_t)o * (2 * Hd); bias = attn_b[o]; }
        else        { int j = o - Hd; wrow = Whh + (size_t)j * Hd; bias = bhh[j]; }
        float acc = 0.f;
        for (int k = lane; k < Hd; k += 32) acc += wrow[k] * sh[k];
        acc = warp_sum(acc);
        if (lane == 0) {
            if (o < Hd) u[(size_t)b * Hd + o] = acc + bias;
            else        gh[(size_t)b * G3H + (o - Hd)] = acc + bias;
        }
    }
}

// ---------------- tiled fp32 GEMM: C[M,N] = A[M,512] @ B[512,N] ----------------
// 128x128 block tile, 8x8 per thread, BK=8. M % 128 == 0, N % 8 == 0 required.
__global__ __launch_bounds__(256) void gemm_k(const float* __restrict__ A,
                                              const float* __restrict__ Bm,
                                              float* __restrict__ C, int M, int N) {
    __shared__ float As[8][132];
    __shared__ float Bs[8][128];
    int tid = threadIdx.x;
    int tx = tid & 15, ty = tid >> 4;
    int m0 = blockIdx.y * 128, n0 = blockIdx.x * 128;

    float acc[8][8];
    #pragma unroll
    for (int i = 0; i < 8; i++)
        #pragma unroll
        for (int j = 0; j < 8; j++) acc[i][j] = 0.f;

    int arow = tid >> 1, ak = (tid & 1) * 4;          // A: 128 rows x 8 k
    int brow = tid >> 5, bn = (tid & 31) * 4;         // B: 8 k x 128 n
    const float* Aptr = A + (size_t)(m0 + arow) * 512 + ak;

    for (int k0 = 0; k0 < 512; k0 += 8) {
        float4 a4 = *(const float4*)(Aptr + k0);
        As[ak + 0][arow] = a4.x; As[ak + 1][arow] = a4.y;
        As[ak + 2][arow] = a4.z; As[ak + 3][arow] = a4.w;
        int ncol = n0 + bn;
        float4 b4 = make_float4(0.f, 0.f, 0.f, 0.f);
        if (ncol < N) b4 = *(const float4*)(Bm + (size_t)(k0 + brow) * N + ncol);
        *(float4*)&Bs[brow][bn] = b4;
        __syncthreads();
        #pragma unroll
        for (int k = 0; k < 8; k++) {
            float4 a0 = *(const float4*)&As[k][ty * 8];
            float4 a1 = *(const float4*)&As[k][ty * 8 + 4];
            float4 b0 = *(const float4*)&Bs[k][tx * 8];
            float4 b1 = *(const float4*)&Bs[k][tx * 8 + 4];
            float av[8] = {a0.x, a0.y, a0.z, a0.w, a1.x, a1.y, a1.z, a1.w};
            float bv[8] = {b0.x, b0.y, b0.z, b0.w, b1.x, b1.y, b1.z, b1.w};
            #pragma unroll
            for (int i = 0; i < 8; i++)
                #pragma unroll
                for (int j = 0; j < 8; j++) acc[i][j] += av[i] * bv[j];
        }
        __syncthreads();
    }
    #pragma unroll
    for (int i = 0; i < 8; i++) {
        int row = m0 + ty * 8 + i;
        float* crow = C + (size_t)row * N;
        int c0 = n0 + tx * 8;
        if (c0 < N) {  // N % 8 == 0 -> whole 8-wide strip in/out together
            *(float4*)(crow + c0)     = make_float4(acc[i][0], acc[i][1], acc[i][2], acc[i][3]);
            *(float4*)(crow + c0 + 4) = make_float4(acc[i][4], acc[i][5], acc[i][6], acc[i][7]);
        }
    }
}

// ---------------- attention scores: score[t] = sum_j v[j]*tanh(E[t,j]+u[b,j]); mask ids==0 ----------------
__global__ void score_k(const float* __restrict__ E, const int* __restrict__ ids,
                        const float* __restrict__ u, const float* __restrict__ v,
                        float* __restrict__ score, int T) {
    int tok = blockIdx.x * 8 + (threadIdx.x >> 5);
    int lane = threadIdx.x & 31;
    int b = tok / T;
    const float* e = E + (size_t)tok * Hd;
    const float* ub = u + (size_t)b * Hd;
    float acc = 0.f;
    for (int j = lane; j < Hd; j += 32) acc += v[j] * tanhf(e[j] + ub[j]);
    acc = warp_sum(acc);
    if (lane == 0) score[tok] = (ids[tok] == 0) ? NEGV : acc;
}

// ---------------- softmax over T then ctx = a @ enc, written into x at xoff ----------------
__global__ void softmax_ctx_k(const float* __restrict__ score, const float* __restrict__ enc,
                              float* __restrict__ x, int T, int xoff) {
    int b = blockIdx.x, tid = threadIdx.x;
    __shared__ float sw[256];
    __shared__ float red[256];
    float sv = (tid < T) ? score[(size_t)b * T + tid] : -3.0e38f;
    red[tid] = sv; __syncthreads();
    for (int s = 128; s; s >>= 1) { if (tid < s) red[tid] = fmaxf(red[tid], red[tid + s]); __syncthreads(); }
    float m = red[0]; __syncthreads();
    float e = (tid < T) ? expf(sv - m) : 0.f;
    red[tid] = e; __syncthreads();
    for (int s = 128; s; s >>= 1) { if (tid < s) red[tid] += red[tid + s]; __syncthreads(); }
    float Z = red[0]; __syncthreads();
    sw[tid] = e / Z; __syncthreads();
    for (int h = tid; h < Hd; h += 256) {
        float acc = 0.f;
        const float* ep = enc + (size_t)b * T * Hd + h;
        for (int t = 0; t < T; t++) acc += sw[t] * ep[(size_t)t * Hd];
        x[(size_t)b * XD + xoff + h] = acc;
    }
}

// ---------------- x: emb + db slots ----------------
__global__ void fill_x_k(const int* __restrict__ w, const float* __restrict__ emb_table,
                         const float* __restrict__ db, float* __restrict__ x) {
    int b = blockIdx.x, tid = threadIdx.x;
    int wid = w[b];
    for (int i = tid; i < Ed; i += 256) x[(size_t)b * XD + i] = emb_table[(size_t)wid * Ed + i];
    for (int i = tid; i < PTRd; i += 256) x[(size_t)b * XD + Ed + 3 * Hd + i] = db[(size_t)b * PTRd + i];
}

// ---------------- gi = Wih@x + bih, then GRU cell -> hnew ----------------
__global__ void gru_k(const float* __restrict__ x, const float* __restrict__ Wih,
                      const float* __restrict__ bih, const float* __restrict__ gh,
                      const float* __restrict__ h0, float* __restrict__ hnew) {
    int b = blockIdx.x;
    __shared__ float sx[XD];
    __shared__ float sgi[G3H];
    for (int i = threadIdx.x; i < XD; i += 256) sx[i] = x[(size_t)b * XD + i];
    __syncthreads();
    int warp = threadIdx.x >> 5, lane = threadIdx.x & 31;
    for (int o = warp; o < G3H; o += 8) {
        const float* wrow = Wih + (size_t)o * XD;
        float acc = 0.f;
        for (int k = lane; k < XD; k += 32) acc += wrow[k] * sx[k];
        acc = warp_sum(acc);
        if (lane == 0) sgi[o] = acc + bih[o];
    }
    __syncthreads();
    const float* ghb = gh + (size_t)b * G3H;
    for (int j = threadIdx.x; j < Hd; j += 256) {
        float r = sigmoidf_(sgi[j] + ghb[j]);
        float z = sigmoidf_(sgi[Hd + j] + ghb[Hd + j]);
        float n = tanhf(sgi[2 * Hd + j] + r * ghb[2 * Hd + j]);
        hnew[(size_t)b * Hd + j] = (1.f - z) * n + z * h0[(size_t)b * Hd + j];
    }
}

// ---------------- cp_raw[b,t] = sum_j hnew[b,j]*tanh(BCP[b,t,j]+Wcb[j]); mask ----------------
__global__ void cpraw_k(const float* __restrict__ BCP, const float* __restrict__ Wcb,
                        const float* __restrict__ hnew, const int* __restrict__ ids,
                        float* __restrict__ cpr) {
    int tok = blockIdx.x * 8 + (threadIdx.x >> 5);
    int lane = threadIdx.x & 31;
    int b = tok / TBt;
    const float* e = BCP + (size_t)tok * Hd;
    const float* hn = hnew + (size_t)b * Hd;
    float acc = 0.f;
    for (int j = lane; j < Hd; j += 32) acc += hn[j] * tanhf(e[j] + Wcb[j]);
    acc = warp_sum(acc);
    if (lane == 0) cpr[tok] = (ids[tok] == 0) ? NEGV : acc;
}

// ---------------- final: log_softmax over [gen | cps], logaddexp + OOV scatter ----------------
__global__ void final_k(const float* __restrict__ gen, const float* __restrict__ genb,
                        const float* __restrict__ cpr, const int* __restrict__ nounk,
                        float* __restrict__ out) {
    int b = blockIdx.x, tid = threadIdx.x;
    __shared__ float Lg[Vd];
    __shared__ float Lc[Vd + TBt];
    __shared__ float addv[VOOVd - Vd];
    __shared__ float red[256];
    for (int n = tid; n < Vd; n += 256) Lg[n] = gen[(size_t)b * Vd + n] + genb[n];
    for (int n = tid; n < Vd + TBt; n += 256) Lc[n] = 0.f;
    for (int n = tid; n < VOOVd - Vd; n += 256) addv[n] = 0.f;
    __syncthreads();
    if (tid == 0) {  // deterministic serial scatter (Tb=128)
        for (int t = 0; t < TBt; t++) {
            int nk = nounk[(size_t)b * TBt + t];
            int col = (nk < Vd) ? nk : (Vd + t);
            Lc[col] += cpr[(size_t)b * TBt + t];
        }
    }
    __syncthreads();
    float lm = -3.0e38f;
    for (int n = tid; n < 2 * Vd + TBt; n += 256) {
        float v = (n < Vd) ? Lg[n] : Lc[n - Vd];
        lm = fmaxf(lm, v);
    }
    red[tid] = lm; __syncthreads();
    for (int s = 128; s; s >>= 1) { if (tid < s) red[tid] = fmaxf(red[tid], red[tid + s]); __syncthreads(); }
    float M = red[0]; __syncthreads();
    float ls = 0.f;
    for (int n = tid; n < 2 * Vd + TBt; n += 256) {
        float v = (n < Vd) ? Lg[n] : Lc[n - Vd];
        ls += expf(v - M);
    }
    red[tid] = ls; __syncthreads();
    for (int s = 128; s; s >>= 1) { if (tid < s) red[tid] += red[tid + s]; __syncthreads(); }
    float logZ = M + logf(red[0]); __syncthreads();
    if (tid == 0) {
        for (int t = 0; t < TBt; t++) {
            int nk = nounk[(size_t)b * TBt + t];
            if (nk >= Vd) addv[nk - Vd] += expf(Lc[Vd + t] - logZ);
        }
    }
    __syncthreads();
    for (int n = tid; n < VOOVd; n += 256) {
        float val;
        if (n < Vd) {
            float a = Lg[n] - logZ;
            float c = Lc[n] - logZ;
            float mm = fmaxf(a, c);
            val = mm + log1pf(expf(-fabsf(a - c)));
        } else {
            float v = addv[n - Vd];
            val = (v > 0.f) ? logf(fmaxf(v, 1e-38f)) : NEGV;
        }
        out[(size_t)b * VOOVd + n] = val;
    }
}

// ---------------- host ----------------
extern "C" void kernel_launch(void* const* d_in, const int* in_sizes, int n_in,
                              void* d_out, int out_size) {
    const int*   dec_last_w = (const int*)  d_in[0];
    const float* h0         = (const float*)d_in[1];
    const float* usdx_h     = (const float*)d_in[2];
    const float* bspn_h     = (const float*)d_in[3];
    const float* pv_h       = (const float*)d_in[4];
    const float* db         = (const float*)d_in[5];
    const int*   usdx_ids   = (const int*)  d_in[6];
    const int*   bspn_ids   = (const int*)  d_in[7];
    const int*   pv_ids     = (const int*)  d_in[8];
    const int*   nounk      = (const int*)  d_in[9];
    // d_in[10] = bspn_onehot: intentionally unused (semantics rebuilt from nounk)
    const float* emb        = (const float*)d_in[11];
    const float* attn_W     = (const float*)d_in[12];
    const float* attn_b     = (const float*)d_in[13];
    const float* v_w        = (const float*)d_in[14];
    const float* Wc         = (const float*)d_in[15];
    const float* Wcb        = (const float*)d_in[16];
    const float* Wg         = (const float*)d_in[17];
    const float* Wgb        = (const float*)d_in[18];
    const float* Wih        = (const float*)d_in[19];
    const float* Whh        = (const float*)d_in[20];
    const float* bih        = (const float*)d_in[21];
    const float* bhh        = (const float*)d_in[22];
    float* out = (float*)d_out;

    float* S = nullptr;
    cudaGetSymbolAddress((void**)&S, g_scratch);
    float* W2T  = S + OFF_W2T;
    float* WCT  = S + OFF_WCT;
    float* WGT  = S + OFF_WGT;
    float* U    = S + OFF_U;
    float* GH   = S + OFF_GH;
    float* EU   = S + OFF_EU;
    float* EB   = S + OFF_EB;
    float* EP   = S + OFF_EP;
    float* BCP  = S + OFF_BCP;
    float* SU   = S + OFF_SU;
    float* SB   = S + OFF_SB;
    float* SP   = S + OFF_SP;
    float* X    = S + OFF_X;
    float* HNEW = S + OFF_HNEW;
    float* GEN  = S + OFF_GEN;
    float* CPR  = S + OFF_CPR;

    // weight transposes (recomputed every call: deterministic, cheap)
    transpose_k<<<(512 * 512 + 255) / 256, 256>>>(attn_W, W2T, 512, 512, 2 * Hd, Hd);
    transpose_k<<<(512 * 512 + 255) / 256, 256>>>(Wc, WCT, 512, 512, Hd, 0);
    transpose_k<<<(512 * 3000 + 255) / 256, 256>>>(Wg, WGT, 3000, 512, Hd, 0);

    prep_k<<<Bn, 256>>>(h0, attn_W, attn_b, Whh, bhh, U, GH);

    gemm_k<<<dim3(4, (Bn * TU) / 128), 256>>>(usdx_h, W2T, EU, Bn * TU, 512);
    gemm_k<<<dim3(4, (Bn * TBt) / 128), 256>>>(bspn_h, W2T, EB, Bn * TBt, 512);
    gemm_k<<<dim3(4, (Bn * TPt) / 128), 256>>>(pv_h, W2T, EP, Bn * TPt, 512);
    gemm_k<<<dim3(4, (Bn * TBt) / 128), 256>>>(bspn_h, WCT, BCP, Bn * TBt, 512);

    score_k<<<(Bn * TU) / 8, 256>>>(EU, usdx_ids, U, v_w, SU, TU);
    score_k<<<(Bn * TBt) / 8, 256>>>(EB, bspn_ids, U, v_w, SB, TBt);
    score_k<<<(Bn * TPt) / 8, 256>>>(EP, pv_ids, U, v_w, SP, TPt);

    softmax_ctx_k<<<Bn, 256>>>(SU, usdx_h, X, TU, Ed);
    softmax_ctx_k<<<Bn, 256>>>(SB, bspn_h, X, TBt, Ed + Hd);
    softmax_ctx_k<<<Bn, 256>>>(SP, pv_h, X, TPt, Ed + 2 * Hd);
    fill_x_k<<<Bn, 256>>>(dec_last_w, emb, db, X);

    gru_k<<<Bn, 256>>>(X, Wih, bih, GH, h0, HNEW);

    gemm_k<<<dim3((3000 + 127) / 128, 1), 256>>>(HNEW, WGT, GEN, Bn, 3000);
    cpraw_k<<<(Bn * TBt) / 8, 256>>>(BCP, Wcb, HNEW, bspn_ids, CPR);

    final_k<<<Bn, 256>>>(GEN, Wgb, CPR, nounk, out);
}

// round 2
// speedup vs baseline: 4.5844x; 4.5844x over previous
#include <cuda_runtime.h>
#include <cuda_bf16.h>
#include <math.h>
#include <stdint.h>

// ---------------- problem constants ----------------
#define Bn    128
#define TU    256
#define TBt   128
#define TPt   64
#define Hd    512
#define Ed    512
#define Vd    3000
#define VOOVd 3400
#define PTRd  32
#define XD    2080   // E + 3H + PTR
#define G3H   1536
#define NEGV  (-1e20f)

// ---------------- fp32 scratch ----------------
constexpr size_t OFF_U    = 0;                            // B x H
constexpr size_t OFF_GH   = OFF_U    + (size_t)Bn*Hd;     // B x 3H
constexpr size_t OFF_EU   = OFF_GH   + (size_t)Bn*G3H;    // B*TU x H
constexpr size_t OFF_EB   = OFF_EU   + (size_t)Bn*TU*Hd;
constexpr size_t OFF_EP   = OFF_EB   + (size_t)Bn*TBt*Hd;
constexpr size_t OFF_BCP  = OFF_EP   + (size_t)Bn*TPt*Hd;
constexpr size_t OFF_SU   = OFF_BCP  + (size_t)Bn*TBt*Hd;
constexpr size_t OFF_SB   = OFF_SU   + (size_t)Bn*TU;
constexpr size_t OFF_SP   = OFF_SB   + (size_t)Bn*TBt;
constexpr size_t OFF_X    = OFF_SP   + (size_t)Bn*TPt;    // B x 2080
constexpr size_t OFF_GI   = OFF_X    + (size_t)Bn*XD;     // B x 3H
constexpr size_t OFF_HNEW = OFF_GI   + (size_t)Bn*G3H;
constexpr size_t OFF_GEN  = OFF_HNEW + (size_t)Bn*Hd;     // B x V (bias included)
constexpr size_t OFF_CPR  = OFF_GEN  + (size_t)Bn*Vd;
constexpr size_t TOT_F32  = OFF_CPR  + (size_t)Bn*TBt;
__device__ float g_scratch[TOT_F32];

// ---------------- bf16 scratch ----------------
constexpr size_t BOFF_EU  = 0;                              // enc usdx
constexpr size_t BOFF_EB  = BOFF_EU + (size_t)Bn*TU*Hd;
constexpr size_t BOFF_EP  = BOFF_EB + (size_t)Bn*TBt*Hd;
constexpr size_t BOFF_W1  = BOFF_EP + (size_t)Bn*TPt*Hd;    // 512x512
constexpr size_t BOFF_W2  = BOFF_W1 + (size_t)512*512;
constexpr size_t BOFF_WC  = BOFF_W2 + (size_t)512*512;
constexpr size_t BOFF_WG  = BOFF_WC + (size_t)512*512;      // 3000x512
constexpr size_t BOFF_WIH = BOFF_WG + (size_t)3000*512;     // 1536x2080
constexpr size_t BOFF_WHH = BOFF_WIH+ (size_t)1536*2080;    // 1536x512
constexpr size_t BOFF_H0  = BOFF_WHH+ (size_t)1536*512;     // 128x512
constexpr size_t BOFF_X   = BOFF_H0 + (size_t)Bn*Hd;        // 128x2080
constexpr size_t BOFF_HN  = BOFF_X  + (size_t)Bn*XD;        // 128x512
constexpr size_t TOT_BF   = BOFF_HN + (size_t)Bn*Hd;
__device__ __nv_bfloat16 g_bf[TOT_BF];

__device__ __forceinline__ float warp_sum(float v) {
    #pragma unroll
    for (int s = 16; s; s >>= 1) v += __shfl_down_sync(0xffffffffu, v, s);
    return v;
}
__device__ __forceinline__ float sigmoidf_(float x) { return 1.0f / (1.0f + expf(-x)); }

// ---------------- fp32 -> bf16 converts ----------------
__global__ void f2bf_k(const float* __restrict__ in, __nv_bfloat16* __restrict__ outp, int n4) {
    int i = blockIdx.x * 256 + threadIdx.x;
    if (i >= n4) return;
    float4 v = ((const float4*)in)[i];
    __nv_bfloat162 lo = __floats2bfloat162_rn(v.x, v.y);
    __nv_bfloat162 hi = __floats2bfloat162_rn(v.z, v.w);
    ((__nv_bfloat162*)outp)[2*i]   = lo;
    ((__nv_bfloat162*)outp)[2*i+1] = hi;
}
// strided (rows x cols taken from in[r*instride + coloff + c])
__global__ void f2bf_stride_k(const float* __restrict__ in, __nv_bfloat16* __restrict__ outp,
                              int rows, int cols, int instride, int coloff) {
    int i = blockIdx.x * 256 + threadIdx.x;
    if (i >= rows * cols) return;
    int r = i / cols, c = i % cols;
    outp[i] = __float2bfloat16(in[(size_t)r * instride + coloff + c]);
}

// ---------------- bf16 mma GEMM: C[M,N] = A[M,K] @ W[N,K]^T (+bias) ----------------
__device__ __forceinline__ uint32_t sptr(const void* p) {
    return (uint32_t)__cvta_generic_to_shared(p);
}
__device__ __forceinline__ void ldsm_x4(uint32_t& r0, uint32_t& r1, uint32_t& r2, uint32_t& r3, uint32_t a) {
    asm volatile("ldmatrix.sync.aligned.m8n8.x4.shared.b16 {%0,%1,%2,%3}, [%4];\n"
                 : "=r"(r0), "=r"(r1), "=r"(r2), "=r"(r3) : "r"(a));
}
__device__ __forceinline__ void mma_bf16(float* d, const uint32_t* a, const uint32_t* b) {
    asm volatile("mma.sync.aligned.m16n8k16.row.col.f32.bf16.bf16.f32 "
                 "{%0,%1,%2,%3},{%4,%5,%6,%7},{%8,%9},{%0,%1,%2,%3};\n"
                 : "+f"(d[0]), "+f"(d[1]), "+f"(d[2]), "+f"(d[3])
                 : "r"(a[0]), "r"(a[1]), "r"(a[2]), "r"(a[3]), "r"(b[0]), "r"(b[1]));
}

#define GPAD 40  // smem row stride in bf16 (80B -> conflict-free ldmatrix)

__global__ __launch_bounds__(256, 2) void gemm_bf16_k(
    const __nv_bfloat16* __restrict__ A, const __nv_bfloat16* __restrict__ Bw,
    const float* __restrict__ bias, float* __restrict__ C, int M, int N, int K)
{
    __shared__ __align__(16) __nv_bfloat16 As[128 * GPAD];
    __shared__ __align__(16) __nv_bfloat16 Bs[128 * GPAD];
    int tid = threadIdx.x;
    int warp = tid >> 5, lane = tid & 31;
    int m0 = blockIdx.y * 128, n0 = blockIdx.x * 128;
    int wm = (warp >> 2) * 64, wn = (warp & 3) * 32;

    float acc[4][4][4];
    #pragma unroll
    for (int i = 0; i < 4; i++)
        #pragma unroll
        for (int j = 0; j < 4; j++)
            #pragma unroll
            for (int q = 0; q < 4; q++) acc[i][j][q] = 0.f;

    for (int k0 = 0; k0 < K; k0 += 32) {
        #pragma unroll
        for (int s = 0; s < 2; s++) {
            int idx = tid + s * 256;            // 512 chunks: 128 rows x 4 x (8 bf16)
            int r = idx >> 2, c = (idx & 3) * 8;
            uint4 va = *(const uint4*)(A + (size_t)(m0 + r) * K + k0 + c);
            *(uint4*)(As + r * GPAD + c) = va;
            int gn = n0 + r;
            uint4 vb = make_uint4(0u, 0u, 0u, 0u);
            if (gn < N) vb = *(const uint4*)(Bw + (size_t)gn * K + k0 + c);
            *(uint4*)(Bs + r * GPAD + c) = vb;
        }
        __syncthreads();
        #pragma unroll
        for (int kk = 0; kk < 2; kk++) {
            int kb = kk * 16;
            uint32_t afr[4][4], bfr[4][2];
            #pragma unroll
            for (int mt = 0; mt < 4; mt++) {
                int row = wm + mt * 16 + (lane & 15);
                int col = kb + (lane >> 4) * 8;
                ldsm_x4(afr[mt][0], afr[mt][1], afr[mt][2], afr[mt][3],
                        sptr(As + row * GPAD + col));
            }
            #pragma unroll
            for (int p = 0; p < 2; p++) {
                int row = wn + p * 16 + (lane & 7) + ((lane >> 4) & 1) * 8;
                int col = kb + ((lane >> 3) & 1) * 8;
                ldsm_x4(bfr[2*p][0], bfr[2*p][1], bfr[2*p+1][0], bfr[2*p+1][1],
                        sptr(Bs + row * GPAD + col));
            }
            #pragma unroll
            for (int mt = 0; mt < 4; mt++)
                #pragma unroll
                for (int nt = 0; nt < 4; nt++)
                    mma_bf16(acc[mt][nt], afr[mt], bfr[nt]);
        }
        __syncthreads();
    }

    #pragma unroll
    for (int mt = 0; mt < 4; mt++) {
        int r = m0 + wm + mt * 16 + (lane >> 2);
        #pragma unroll
        for (int nt = 0; nt < 4; nt++) {
            int col = n0 + wn + nt * 8 + (lane & 3) * 2;
            if (col < N) {
                float b0 = bias ? bias[col] : 0.f;
                float b1 = bias ? bias[col + 1] : 0.f;
                *(float2*)(C + (size_t)r * N + col) =
                    make_float2(acc[mt][nt][0] + b0, acc[mt][nt][1] + b1);
                *(float2*)(C + (size_t)(r + 8) * N + col) =
                    make_float2(acc[mt][nt][2] + b0, acc[mt][nt][3] + b1);
            }
        }
    }
}

// ---------------- attention scores ----------------
__global__ void score_k(const float* __restrict__ E, const int* __restrict__ ids,
                        const float* __restrict__ u, const float* __restrict__ v,
                        float* __restrict__ score, int T) {
    int tok = blockIdx.x * 8 + (threadIdx.x >> 5);
    int lane = threadIdx.x & 31;
    int b = tok / T;
    const float* e = E + (size_t)tok * Hd;
    const float* ub = u + (size_t)b * Hd;
    float acc = 0.f;
    #pragma unroll 4
    for (int j = lane; j < Hd; j += 32) acc += v[j] * tanhf(e[j] + ub[j]);
    acc = warp_sum(acc);
    if (lane == 0) score[tok] = (ids[tok] == 0) ? NEGV : acc;
}

// ---------------- softmax over T then ctx = a @ enc; grid (Bn, 2), 256 h each ----------------
__global__ void softmax_ctx_k(const float* __restrict__ score, const float* __restrict__ enc,
                              float* __restrict__ x, int T, int xoff) {
    int b = blockIdx.x, chunk = blockIdx.y, tid = threadIdx.x;
    __shared__ float sw[256];
    __shared__ float red[256];
    float sv = (tid < T) ? score[(size_t)b * T + tid] : -3.0e38f;
    red[tid] = sv; __syncthreads();
    for (int s = 128; s; s >>= 1) { if (tid < s) red[tid] = fmaxf(red[tid], red[tid + s]); __syncthreads(); }
    float m = red[0]; __syncthreads();
    float e = (tid < T) ? expf(sv - m) : 0.f;
    red[tid] = e; __syncthreads();
    for (int s = 128; s; s >>= 1) { if (tid < s) red[tid] += red[tid + s]; __syncthreads(); }
    float Z = red[0]; __syncthreads();
    sw[tid] = e / Z; __syncthreads();
    int h = chunk * 256 + tid;
    float acc = 0.f;
    const float* ep = enc + (size_t)b * T * Hd + h;
    #pragma unroll 4
    for (int t = 0; t < T; t++) acc += sw[t] * ep[(size_t)t * Hd];
    x[(size_t)b * XD + xoff + h] = acc;
}

// ---------------- x: emb + db slots ----------------
__global__ void fill_x_k(const int* __restrict__ w, const float* __restrict__ emb_table,
                         const float* __restrict__ db, float* __restrict__ x) {
    int b = blockIdx.x, tid = threadIdx.x;
    int wid = w[b];
    for (int i = tid; i < Ed; i += 256) x[(size_t)b * XD + i] = emb_table[(size_t)wid * Ed + i];
    for (int i = tid; i < PTRd; i += 256) x[(size_t)b * XD + Ed + 3 * Hd + i] = db[(size_t)b * PTRd + i];
}

// ---------------- GRU cell (gi, gh already include biases) ----------------
__global__ void gru_cell_k(const float* __restrict__ gi, const float* __restrict__ gh,
                           const float* __restrict__ h0, float* __restrict__ hnew,
                           __nv_bfloat16* __restrict__ hnbf) {
    int i = blockIdx.x * 256 + threadIdx.x;   // i over B*H
    if (i >= Bn * Hd) return;
    int b = i / Hd, j = i % Hd;
    const float* gib = gi + (size_t)b * G3H;
    const float* ghb = gh + (size_t)b * G3H;
    float r = sigmoidf_(gib[j] + ghb[j]);
    float z = sigmoidf_(gib[Hd + j] + ghb[Hd + j]);
    float n = tanhf(gib[2 * Hd + j] + r * ghb[2 * Hd + j]);
    float hv = (1.f - z) * n + z * h0[i];
    hnew[i] = hv;
    hnbf[i] = __float2bfloat16(hv);
}

// ---------------- cp_raw (Wcopy bias already folded into BCP) ----------------
__global__ void cpraw_k(const float* __restrict__ BCP, const float* __restrict__ hnew,
                        const int* __restrict__ ids, float* __restrict__ cpr) {
    int tok = blockIdx.x * 8 + (threadIdx.x >> 5);
    int lane = threadIdx.x & 31;
    int b = tok / TBt;
    const float* e = BCP + (size_t)tok * Hd;
    const float* hn = hnew + (size_t)b * Hd;
    float acc = 0.f;
    #pragma unroll 4
    for (int j = lane; j < Hd; j += 32) acc += hn[j] * tanhf(e[j]);
    acc = warp_sum(acc);
    if (lane == 0) cpr[tok] = (ids[tok] == 0) ? NEGV : acc;
}

// ---------------- final: log_softmax over [gen | cps], logaddexp + OOV scatter ----------------
__global__ void final_k(const float* __restrict__ gen, const float* __restrict__ cpr,
                        const int* __restrict__ nounk, float* __restrict__ out) {
    int b = blockIdx.x, tid = threadIdx.x;
    __shared__ float Lg[Vd];
    __shared__ float Lc[Vd + TBt];
    __shared__ float addv[VOOVd - Vd];
    __shared__ float red[256];
    for (int n = tid; n < Vd; n += 256) Lg[n] = gen[(size_t)b * Vd + n];
    for (int n = tid; n < Vd + TBt; n += 256) Lc[n] = 0.f;
    for (int n = tid; n < VOOVd - Vd; n += 256) addv[n] = 0.f;
    __syncthreads();
    if (tid == 0) {  // deterministic serial scatter (Tb=128)
        for (int t = 0; t < TBt; t++) {
            int nk = nounk[(size_t)b * TBt + t];
            int col = (nk < Vd) ? nk : (Vd + t);
            Lc[col] += cpr[(size_t)b * TBt + t];
        }
    }
    __syncthreads();
    float lm = -3.0e38f;
    for (int n = tid; n < 2 * Vd + TBt; n += 256) {
        float v = (n < Vd) ? Lg[n] : Lc[n - Vd];
        lm = fmaxf(lm, v);
    }
    red[tid] = lm; __syncthreads();
    for (int s = 128; s; s >>= 1) { if (tid < s) red[tid] = fmaxf(red[tid], red[tid + s]); __syncthreads(); }
    float M = red[0]; __syncthreads();
    float ls = 0.f;
    for (int n = tid; n < 2 * Vd + TBt; n += 256) {
        float v = (n < Vd) ? Lg[n] : Lc[n - Vd];
        ls += expf(v - M);
    }
    red[tid] = ls; __syncthreads();
    for (int s = 128; s; s >>= 1) { if (tid < s) red[tid] += red[tid + s]; __syncthreads(); }
    float logZ = M + logf(red[0]); __syncthreads();
    if (tid == 0) {
        for (int t = 0; t < TBt; t++) {
            int nk = nounk[(size_t)b * TBt + t];
            if (nk >= Vd) addv[nk - Vd] += expf(Lc[Vd + t] - logZ);
        }
    }
    __syncthreads();
    for (int n = tid; n < VOOVd; n += 256) {
        float val;
        if (n < Vd) {
            float a = Lg[n] - logZ;
            float c = Lc[n] - logZ;
            float mm = fmaxf(a, c);
            val = mm + log1pf(expf(-fabsf(a - c)));
        } else {
            float v = addv[n - Vd];
            val = (v > 0.f) ? logf(fmaxf(v, 1e-38f)) : NEGV;
        }
        out[(size_t)b * VOOVd + n] = val;
    }
}

// ---------------- host ----------------
static inline int cdiv(int a, int b) { return (a + b - 1) / b; }

extern "C" void kernel_launch(void* const* d_in, const int* in_sizes, int n_in,
                              void* d_out, int out_size) {
    const int*   dec_last_w = (const int*)  d_in[0];
    const float* h0         = (const float*)d_in[1];
    const float* usdx_h     = (const float*)d_in[2];
    const float* bspn_h     = (const float*)d_in[3];
    const float* pv_h       = (const float*)d_in[4];
    const float* db         = (const float*)d_in[5];
    const int*   usdx_ids   = (const int*)  d_in[6];
    const int*   bspn_ids   = (const int*)  d_in[7];
    const int*   pv_ids     = (const int*)  d_in[8];
    const int*   nounk      = (const int*)  d_in[9];
    // d_in[10] = bspn_onehot: unused (semantics rebuilt from nounk)
    const float* emb        = (const float*)d_in[11];
    const float* attn_W     = (const float*)d_in[12];
    const float* attn_b     = (const float*)d_in[13];
    const float* v_w        = (const float*)d_in[14];
    const float* Wc         = (const float*)d_in[15];
    const float* Wcb        = (const float*)d_in[16];
    const float* Wg         = (const float*)d_in[17];
    const float* Wgb        = (const float*)d_in[18];
    const float* Wih        = (const float*)d_in[19];
    const float* Whh        = (const float*)d_in[20];
    const float* bih        = (const float*)d_in[21];
    const float* bhh        = (const float*)d_in[22];
    float* out = (float*)d_out;

    float* S = nullptr;
    cudaGetSymbolAddress((void**)&S, g_scratch);
    __nv_bfloat16* Bf = nullptr;
    cudaGetSymbolAddress((void**)&Bf, g_bf);

    float* U    = S + OFF_U;
    float* GH   = S + OFF_GH;
    float* EU   = S + OFF_EU;
    float* EB   = S + OFF_EB;
    float* EP   = S + OFF_EP;
    float* BCP  = S + OFF_BCP;
    float* SU   = S + OFF_SU;
    float* SB   = S + OFF_SB;
    float* SP   = S + OFF_SP;
    float* X    = S + OFF_X;
    float* GI   = S + OFF_GI;
    float* HNEW = S + OFF_HNEW;
    float* GEN  = S + OFF_GEN;
    float* CPR  = S + OFF_CPR;

    __nv_bfloat16* bEU  = Bf + BOFF_EU;
    __nv_bfloat16* bEB  = Bf + BOFF_EB;
    __nv_bfloat16* bEP  = Bf + BOFF_EP;
    __nv_bfloat16* bW1  = Bf + BOFF_W1;
    __nv_bfloat16* bW2  = Bf + BOFF_W2;
    __nv_bfloat16* bWC  = Bf + BOFF_WC;
    __nv_bfloat16* bWG  = Bf + BOFF_WG;
    __nv_bfloat16* bWIH = Bf + BOFF_WIH;
    __nv_bfloat16* bWHH = Bf + BOFF_WHH;
    __nv_bfloat16* bH0  = Bf + BOFF_H0;
    __nv_bfloat16* bX   = Bf + BOFF_X;
    __nv_bfloat16* bHN  = Bf + BOFF_HN;

    // converts
    f2bf_k<<<cdiv(Bn*TU*Hd/4, 256), 256>>>(usdx_h, bEU, Bn*TU*Hd/4);
    f2bf_k<<<cdiv(Bn*TBt*Hd/4, 256), 256>>>(bspn_h, bEB, Bn*TBt*Hd/4);
    f2bf_k<<<cdiv(Bn*TPt*Hd/4, 256), 256>>>(pv_h, bEP, Bn*TPt*Hd/4);
    f2bf_stride_k<<<cdiv(512*512, 256), 256>>>(attn_W, bW1, 512, 512, 2*Hd, 0);
    f2bf_stride_k<<<cdiv(512*512, 256), 256>>>(attn_W, bW2, 512, 512, 2*Hd, Hd);
    f2bf_k<<<cdiv(512*512/4, 256), 256>>>(Wc, bWC, 512*512/4);
    f2bf_k<<<cdiv(3000*512/4, 256), 256>>>(Wg, bWG, 3000*512/4);
    f2bf_k<<<cdiv(1536*2080/4, 256), 256>>>(Wih, bWIH, 1536*2080/4);
    f2bf_k<<<cdiv(1536*512/4, 256), 256>>>(Whh, bWHH, 1536*512/4);
    f2bf_k<<<cdiv(Bn*Hd/4, 256), 256>>>(h0, bH0, Bn*Hd/4);

    // small GEMMs: U = h0@W1^T + attn_b ; GH = h0@Whh^T + bhh
    gemm_bf16_k<<<dim3(4, 1), 256>>>(bH0, bW1, attn_b, U, Bn, 512, 512);
    gemm_bf16_k<<<dim3(12, 1), 256>>>(bH0, bWHH, bhh, GH, Bn, G3H, 512);

    // big GEMMs
    gemm_bf16_k<<<dim3(4, (Bn*TU)/128), 256>>>(bEU, bW2, nullptr, EU, Bn*TU, 512, 512);
    gemm_bf16_k<<<dim3(4, (Bn*TBt)/128), 256>>>(bEB, bW2, nullptr, EB, Bn*TBt, 512, 512);
    gemm_bf16_k<<<dim3(4, (Bn*TPt)/128), 256>>>(bEP, bW2, nullptr, EP, Bn*TPt, 512, 512);
    gemm_bf16_k<<<dim3(4, (Bn*TBt)/128), 256>>>(bEB, bWC, Wcb, BCP, Bn*TBt, 512, 512);

    // scores + softmax/ctx
    score_k<<<(Bn*TU)/8, 256>>>(EU, usdx_ids, U, v_w, SU, TU);
    score_k<<<(Bn*TBt)/8, 256>>>(EB, bspn_ids, U, v_w, SB, TBt);
    score_k<<<(Bn*TPt)/8, 256>>>(EP, pv_ids, U, v_w, SP, TPt);
    softmax_ctx_k<<<dim3(Bn, 2), 256>>>(SU, usdx_h, X, TU, Ed);
    softmax_ctx_k<<<dim3(Bn, 2), 256>>>(SB, bspn_h, X, TBt, Ed + Hd);
    softmax_ctx_k<<<dim3(Bn, 2), 256>>>(SP, pv_h, X, TPt, Ed + 2*Hd);
    fill_x_k<<<Bn, 256>>>(dec_last_w, emb, db, X);

    // GRU
    f2bf_k<<<cdiv(Bn*XD/4, 256), 256>>>(X, bX, Bn*XD/4);
    gemm_bf16_k<<<dim3(12, 1), 256>>>(bX, bWIH, bih, GI, Bn, G3H, XD);
    gru_cell_k<<<cdiv(Bn*Hd, 256), 256>>>(GI, GH, h0, HNEW, bHN);

    // heads
    gemm_bf16_k<<<dim3(cdiv(3000, 128), 1), 256>>>(bHN, bWG, Wgb, GEN, Bn, Vd, 512);
    cpraw_k<<<(Bn*TBt)/8, 256>>>(BCP, HNEW, bspn_ids, CPR);

    final_k<<<Bn, 256>>>(GEN, CPR, nounk, out);
}

// round 3
// speedup vs baseline: 5.6266x; 1.2273x over previous
#include <cuda_runtime.h>
#include <cuda_bf16.h>
#include <math.h>
#include <stdint.h>

// ---------------- problem constants ----------------
#define Bn    128
#define TU    256
#define TBt   128
#define TPt   64
#define Hd    512
#define Ed    512
#define Vd    3000
#define VOOVd 3400
#define PTRd  32
#define XD    2080   // E + 3H + PTR
#define G3H   1536
#define NEGV  (-1e20f)

// ---------------- fp32 scratch ----------------
constexpr size_t OFF_U    = 0;                            // B x H
constexpr size_t OFF_GH   = OFF_U    + (size_t)Bn*Hd;     // B x 3H
constexpr size_t OFF_SPU  = OFF_GH   + (size_t)Bn*G3H;    // B*TU x 4 partial scores
constexpr size_t OFF_SPB  = OFF_SPU  + (size_t)Bn*TU*4;
constexpr size_t OFF_SPP  = OFF_SPB  + (size_t)Bn*TBt*4;
constexpr size_t OFF_X    = OFF_SPP  + (size_t)Bn*TPt*4;  // B x 2080
constexpr size_t OFF_GI   = OFF_X    + (size_t)Bn*XD;     // B x 3H
constexpr size_t OFF_HNEW = OFF_GI   + (size_t)Bn*G3H;
constexpr size_t OFF_GEN  = OFF_HNEW + (size_t)Bn*Hd;     // B x V (bias included)
constexpr size_t OFF_CPR  = OFF_GEN  + (size_t)Bn*Vd;
constexpr size_t TOT_F32  = OFF_CPR  + (size_t)Bn*TBt;
__device__ float g_scratch[TOT_F32];

// ---------------- bf16 scratch ----------------
constexpr size_t BOFF_EU   = 0;
constexpr size_t BOFF_EB   = BOFF_EU  + (size_t)Bn*TU*Hd;
constexpr size_t BOFF_EP   = BOFF_EB  + (size_t)Bn*TBt*Hd;
constexpr size_t BOFF_W1   = BOFF_EP  + (size_t)Bn*TPt*Hd;   // 512x512
constexpr size_t BOFF_W2   = BOFF_W1  + (size_t)512*512;
constexpr size_t BOFF_WC   = BOFF_W2  + (size_t)512*512;
constexpr size_t BOFF_WG   = BOFF_WC  + (size_t)512*512;     // 3000x512
constexpr size_t BOFF_WIH  = BOFF_WG  + (size_t)3000*512;    // 1536x2080
constexpr size_t BOFF_WHH  = BOFF_WIH + (size_t)1536*2080;   // 1536x512
constexpr size_t BOFF_H0   = BOFF_WHH + (size_t)1536*512;    // 128x512
constexpr size_t BOFF_X    = BOFF_H0  + (size_t)Bn*Hd;       // 128x2080
constexpr size_t BOFF_HN   = BOFF_X   + (size_t)Bn*XD;       // 128x512
constexpr size_t BOFF_TBCP = BOFF_HN  + (size_t)Bn*Hd;       // 16384x512 tanh(copy)
constexpr size_t TOT_BF    = BOFF_TBCP+ (size_t)Bn*TBt*Hd;
__device__ __nv_bfloat16 g_bf[TOT_BF];

__device__ __forceinline__ float sigmoidf_(float x) { return 1.0f / (1.0f + expf(-x)); }

// ---------------- fp32 -> bf16 converts ----------------
__global__ void f2bf_k(const float* __restrict__ in, __nv_bfloat16* __restrict__ outp, int n4) {
    int i = blockIdx.x * 256 + threadIdx.x;
    if (i >= n4) return;
    float4 v = ((const float4*)in)[i];
    ((__nv_bfloat162*)outp)[2*i]   = __floats2bfloat162_rn(v.x, v.y);
    ((__nv_bfloat162*)outp)[2*i+1] = __floats2bfloat162_rn(v.z, v.w);
}
__global__ void f2bf_stride_k(const float* __restrict__ in, __nv_bfloat16* __restrict__ outp,
                              int rows, int cols, int instride, int coloff) {
    int i = blockIdx.x * 256 + threadIdx.x;
    if (i >= rows * cols) return;
    int r = i / cols, c = i % cols;
    outp[i] = __float2bfloat16(in[(size_t)r * instride + coloff + c]);
}

// ---------------- mma helpers ----------------
__device__ __forceinline__ uint32_t sptr(const void* p) {
    return (uint32_t)__cvta_generic_to_shared(p);
}
__device__ __forceinline__ void ldsm_x4(uint32_t& r0, uint32_t& r1, uint32_t& r2, uint32_t& r3, uint32_t a) {
    asm volatile("ldmatrix.sync.aligned.m8n8.x4.shared.b16 {%0,%1,%2,%3}, [%4];\n"
                 : "=r"(r0), "=r"(r1), "=r"(r2), "=r"(r3) : "r"(a));
}
__device__ __forceinline__ void mma_bf16(float* d, const uint32_t* a, const uint32_t* b) {
    asm volatile("mma.sync.aligned.m16n8k16.row.col.f32.bf16.bf16.f32 "
                 "{%0,%1,%2,%3},{%4,%5,%6,%7},{%8,%9},{%0,%1,%2,%3};\n"
                 : "+f"(d[0]), "+f"(d[1]), "+f"(d[2]), "+f"(d[3])
                 : "r"(a[0]), "r"(a[1]), "r"(a[2]), "r"(a[3]), "r"(b[0]), "r"(b[1]));
}
__device__ __forceinline__ void cp16(uint32_t dst, const void* src, bool pred) {
    int sz = pred ? 16 : 0;
    asm volatile("cp.async.cg.shared.global [%0], [%1], 16, %2;\n"
                 :: "r"(dst), "l"(src), "r"(sz));
}
__device__ __forceinline__ void cp_commit() { asm volatile("cp.async.commit_group;\n"); }
template<int Nw> __device__ __forceinline__ void cp_wait() {
    asm volatile("cp.async.wait_group %0;\n" :: "n"(Nw));
}

#define GPAD 40  // smem row stride in bf16

// MODE 0: C = A@W^T + bias (fp32)
// MODE 1: score partials: spart[(m0+r)*4 + bx] = sum_cols v[c]*tanh(acc + u[b,c])
// MODE 2: Ct = bf16(tanh(acc + bias))
template<int MODE>
__global__ __launch_bounds__(256) void gemm_bf16_k(
    const __nv_bfloat16* __restrict__ A, const __nv_bfloat16* __restrict__ Bw,
    const float* __restrict__ bias, float* __restrict__ C,
    __nv_bfloat16* __restrict__ Ct, float* __restrict__ spart,
    const float* __restrict__ u, const float* __restrict__ v,
    int M, int N, int K, int T)
{
    __shared__ __align__(16) __nv_bfloat16 As[2][128 * GPAD];
    __shared__ __align__(16) __nv_bfloat16 Bs[2][128 * GPAD];
    __shared__ float part[128][4];
    int tid = threadIdx.x;
    int warp = tid >> 5, lane = tid & 31;
    int m0 = blockIdx.y * 128, n0 = blockIdx.x * 128;
    int wm = (warp >> 2) * 64, wn = (warp & 3) * 32;

    float acc[4][4][4];
    #pragma unroll
    for (int i = 0; i < 4; i++)
        #pragma unroll
        for (int j = 0; j < 4; j++)
            #pragma unroll
            for (int q = 0; q < 4; q++) acc[i][j][q] = 0.f;

    // loader: 512 x 16B chunks per tile
    int lr = tid >> 1;                 // 0..127 (two chunks per row via s loop)
    int lc0 = (tid & 1) * 16;          // 0 or 16 (bf16 cols), chunks at +0,+8
    auto load_stage = [&](int st, int k0) {
        #pragma unroll
        for (int s = 0; s < 2; s++) {
            int c = lc0 + s * 8;
            const __nv_bfloat16* ga = A + (size_t)(m0 + lr) * K + k0 + c;
            cp16(sptr(&As[st][lr * GPAD + c]), ga, true);
            int gn = n0 + lr;
            bool pred = gn < N;
            const __nv_bfloat16* gb = Bw + (size_t)(pred ? gn : (N - 1)) * K + k0 + c;
            cp16(sptr(&Bs[st][lr * GPAD + c]), gb, pred);
        }
        cp_commit();
    };

    load_stage(0, 0);
    for (int k0 = 0; k0 < K; k0 += 32) {
        int cur = (k0 >> 5) & 1;
        bool more = (k0 + 32) < K;
        if (more) load_stage(cur ^ 1, k0 + 32);
        if (more) cp_wait<1>(); else cp_wait<0>();
        __syncthreads();
        #pragma unroll
        for (int kk = 0; kk < 2; kk++) {
            int kb = kk * 16;
            uint32_t afr[4][4], bfr[4][2];
            #pragma unroll
            for (int mt = 0; mt < 4; mt++) {
                int row = wm + mt * 16 + (lane & 15);
                int col = kb + (lane >> 4) * 8;
                ldsm_x4(afr[mt][0], afr[mt][1], afr[mt][2], afr[mt][3],
                        sptr(&As[cur][row * GPAD + col]));
            }
            #pragma unroll
            for (int p = 0; p < 2; p++) {
                int row = wn + p * 16 + (lane & 7) + ((lane >> 4) & 1) * 8;
                int col = kb + ((lane >> 3) & 1) * 8;
                ldsm_x4(bfr[2*p][0], bfr[2*p][1], bfr[2*p+1][0], bfr[2*p+1][1],
                        sptr(&Bs[cur][row * GPAD + col]));
            }
            #pragma unroll
            for (int mt = 0; mt < 4; mt++)
                #pragma unroll
                for (int nt = 0; nt < 4; nt++)
                    mma_bf16(acc[mt][nt], afr[mt], bfr[nt]);
        }
        __syncthreads();
    }

    if (MODE == 0) {
        #pragma unroll
        for (int mt = 0; mt < 4; mt++) {
            int r = m0 + wm + mt * 16 + (lane >> 2);
            #pragma unroll
            for (int nt = 0; nt < 4; nt++) {
                int col = n0 + wn + nt * 8 + (lane & 3) * 2;
                if (col < N) {
                    float b0 = bias ? bias[col] : 0.f;
                    float b1 = bias ? bias[col + 1] : 0.f;
                    *(float2*)(C + (size_t)r * N + col) =
                        make_float2(acc[mt][nt][0] + b0, acc[mt][nt][1] + b1);
                    *(float2*)(C + (size_t)(r + 8) * N + col) =
                        make_float2(acc[mt][nt][2] + b0, acc[mt][nt][3] + b1);
                }
            }
        }
    } else if (MODE == 2) {
        #pragma unroll
        for (int mt = 0; mt < 4; mt++) {
            int r = m0 + wm + mt * 16 + (lane >> 2);
            #pragma unroll
            for (int nt = 0; nt < 4; nt++) {
                int col = n0 + wn + nt * 8 + (lane & 3) * 2;
                float b0 = bias[col], b1 = bias[col + 1];
                *(__nv_bfloat162*)(Ct + (size_t)r * N + col) =
                    __floats2bfloat162_rn(tanhf(acc[mt][nt][0] + b0), tanhf(acc[mt][nt][1] + b1));
                *(__nv_bfloat162*)(Ct + (size_t)(r + 8) * N + col) =
                    __floats2bfloat162_rn(tanhf(acc[mt][nt][2] + b0), tanhf(acc[mt][nt][3] + b1));
            }
        }
    } else {  // MODE 1: score partials
        #pragma unroll
        for (int mt = 0; mt < 4; mt++) {
            int r0 = wm + mt * 16 + (lane >> 2);
            int r1 = r0 + 8;
            int b0i = (m0 + r0) / T, b1i = (m0 + r1) / T;
            const float* u0 = u + (size_t)b0i * Hd;
            const float* u1 = u + (size_t)b1i * Hd;
            float ls0 = 0.f, ls1 = 0.f;
            #pragma unroll
            for (int nt = 0; nt < 4; nt++) {
                int col = n0 + wn + nt * 8 + (lane & 3) * 2;
                #pragma unroll
                for (int q = 0; q < 2; q++) {
                    float vv = v[col + q];
                    ls0 += vv * tanhf(acc[mt][nt][q]     + u0[col + q]);
                    ls1 += vv * tanhf(acc[mt][nt][2 + q] + u1[col + q]);
                }
            }
            // reduce across the 4 lanes sharing this row (lane&3)
            #pragma unroll
            for (int s = 1; s < 4; s <<= 1) {
                ls0 += __shfl_xor_sync(0xffffffffu, ls0, s);
                ls1 += __shfl_xor_sync(0xffffffffu, ls1, s);
            }
            if ((lane & 3) == 0) {
                part[r0][warp & 3] = ls0;
                part[r1][warp & 3] = ls1;
            }
        }
        __syncthreads();
        if (tid < 128) {
            float tot = part[tid][0] + part[tid][1] + part[tid][2] + part[tid][3];
            spart[(size_t)(m0 + tid) * 4 + blockIdx.x] = tot;
        }
    }
}

// ---------------- score-sum + mask + softmax + ctx (bf16 enc) ----------------
__global__ void softmax_ctx_k(const float* __restrict__ spart, const int* __restrict__ ids,
                              const __nv_bfloat16* __restrict__ enc,
                              float* __restrict__ x, int T, int xoff) {
    int b = blockIdx.x, chunk = blockIdx.y, tid = threadIdx.x;
    __shared__ float sw[256];
    __shared__ float red[256];
    float sv = -3.0e38f;
    if (tid < T) {
        const float* sp = spart + (size_t)(b * T + tid) * 4;
        sv = sp[0] + sp[1] + sp[2] + sp[3];
        if (ids[(size_t)b * T + tid] == 0) sv = NEGV;
    }
    red[tid] = sv; __syncthreads();
    for (int s = 128; s; s >>= 1) { if (tid < s) red[tid] = fmaxf(red[tid], red[tid + s]); __syncthreads(); }
    float m = red[0]; __syncthreads();
    float e = (tid < T) ? expf(sv - m) : 0.f;
    red[tid] = e; __syncthreads();
    for (int s = 128; s; s >>= 1) { if (tid < s) red[tid] += red[tid + s]; __syncthreads(); }
    float Z = red[0]; __syncthreads();
    sw[tid] = e / Z; __syncthreads();
    int h = chunk * 256 + tid;
    float acc = 0.f;
    const __nv_bfloat16* ep = enc + (size_t)b * T * Hd + h;
    #pragma unroll 4
    for (int t = 0; t < T; t++) acc += sw[t] * __bfloat162float(ep[(size_t)t * Hd]);
    x[(size_t)b * XD + xoff + h] = acc;
}

// ---------------- x: emb + db slots ----------------
__global__ void fill_x_k(const int* __restrict__ w, const float* __restrict__ emb_table,
                         const float* __restrict__ db, float* __restrict__ x) {
    int b = blockIdx.x, tid = threadIdx.x;
    int wid = w[b];
    for (int i = tid; i < Ed; i += 256) x[(size_t)b * XD + i] = emb_table[(size_t)wid * Ed + i];
    for (int i = tid; i < PTRd; i += 256) x[(size_t)b * XD + Ed + 3 * Hd + i] = db[(size_t)b * PTRd + i];
}

// ---------------- GRU cell ----------------
__global__ void gru_cell_k(const float* __restrict__ gi, const float* __restrict__ gh,
                           const float* __restrict__ h0, float* __restrict__ hnew,
                           __nv_bfloat16* __restrict__ hnbf) {
    int i = blockIdx.x * 256 + threadIdx.x;
    if (i >= Bn * Hd) return;
    int b = i / Hd, j = i % Hd;
    const float* gib = gi + (size_t)b * G3H;
    const float* ghb = gh + (size_t)b * G3H;
    float r = sigmoidf_(gib[j] + ghb[j]);
    float z = sigmoidf_(gib[Hd + j] + ghb[Hd + j]);
    float n = tanhf(gib[2 * Hd + j] + r * ghb[2 * Hd + j]);
    float hv = (1.f - z) * n + z * h0[i];
    hnew[i] = hv;
    hnbf[i] = __float2bfloat16(hv);
}

// ---------------- cp_raw: dot(hnew, tanhBCP) ----------------
__global__ void cpraw_k(const __nv_bfloat16* __restrict__ TB, const float* __restrict__ hnew,
                        const int* __restrict__ ids, float* __restrict__ cpr) {
    int tok = blockIdx.x * 8 + (threadIdx.x >> 5);
    int lane = threadIdx.x & 31;
    int b = tok / TBt;
    const __nv_bfloat162* e2 = (const __nv_bfloat162*)(TB + (size_t)tok * Hd);
    const float2* hn2 = (const float2*)(hnew + (size_t)b * Hd);
    float acc = 0.f;
    #pragma unroll 4
    for (int j = lane; j < Hd / 2; j += 32) {
        __nv_bfloat162 p = e2[j];
        float2 h2 = hn2[j];
        acc += h2.x * __bfloat162float(p.x) + h2.y * __bfloat162float(p.y);
    }
    #pragma unroll
    for (int s = 16; s; s >>= 1) acc += __shfl_down_sync(0xffffffffu, acc, s);
    if (lane == 0) cpr[tok] = (ids[tok] == 0) ? NEGV : acc;
}

// ---------------- final: log_softmax over [gen | cps], logaddexp + OOV scatter ----------------
__global__ void final_k(const float* __restrict__ gen, const float* __restrict__ cpr,
                        const int* __restrict__ nounk, float* __restrict__ out) {
    int b = blockIdx.x, tid = threadIdx.x;
    __shared__ float Lg[Vd];
    __shared__ float Lc[Vd + TBt];
    __shared__ float addv[VOOVd - Vd];
    __shared__ float red[256];
    for (int n = tid; n < Vd; n += 256) Lg[n] = gen[(size_t)b * Vd + n];
    for (int n = tid; n < Vd + TBt; n += 256) Lc[n] = 0.f;
    for (int n = tid; n < VOOVd - Vd; n += 256) addv[n] = 0.f;
    __syncthreads();
    if (tid == 0) {
        for (int t = 0; t < TBt; t++) {
            int nk = nounk[(size_t)b * TBt + t];
            int col = (nk < Vd) ? nk : (Vd + t);
            Lc[col] += cpr[(size_t)b * TBt + t];
        }
    }
    __syncthreads();
    float lm = -3.0e38f;
    for (int n = tid; n < 2 * Vd + TBt; n += 256) {
        float v = (n < Vd) ? Lg[n] : Lc[n - Vd];
        lm = fmaxf(lm, v);
    }
    red[tid] = lm; __syncthreads();
    for (int s = 128; s; s >>= 1) { if (tid < s) red[tid] = fmaxf(red[tid], red[tid + s]); __syncthreads(); }
    float M = red[0]; __syncthreads();
    float ls = 0.f;
    for (int n = tid; n < 2 * Vd + TBt; n += 256) {
        float v = (n < Vd) ? Lg[n] : Lc[n - Vd];
        ls += expf(v - M);
    }
    red[tid] = ls; __syncthreads();
    for (int s = 128; s; s >>= 1) { if (tid < s) red[tid] += red[tid + s]; __syncthreads(); }
    float logZ = M + logf(red[0]); __syncthreads();
    if (tid == 0) {
        for (int t = 0; t < TBt; t++) {
            int nk = nounk[(size_t)b * TBt + t];
            if (nk >= Vd) addv[nk - Vd] += expf(Lc[Vd + t] - logZ);
        }
    }
    __syncthreads();
    for (int n = tid; n < VOOVd; n += 256) {
        float val;
        if (n < Vd) {
            float a = Lg[n] - logZ;
            float c = Lc[n] - logZ;
            float mm = fmaxf(a, c);
            val = mm + log1pf(expf(-fabsf(a - c)));
        } else {
            float v = addv[n - Vd];
            val = (v > 0.f) ? logf(fmaxf(v, 1e-38f)) : NEGV;
        }
        out[(size_t)b * VOOVd + n] = val;
    }
}

// ---------------- host ----------------
static inline int cdiv(int a, int b) { return (a + b - 1) / b; }

extern "C" void kernel_launch(void* const* d_in, const int* in_sizes, int n_in,
                              void* d_out, int out_size) {
    const int*   dec_last_w = (const int*)  d_in[0];
    const float* h0         = (const float*)d_in[1];
    const float* usdx_h     = (const float*)d_in[2];
    const float* bspn_h     = (const float*)d_in[3];
    const float* pv_h       = (const float*)d_in[4];
    const float* db         = (const float*)d_in[5];
    const int*   usdx_ids   = (const int*)  d_in[6];
    const int*   bspn_ids   = (const int*)  d_in[7];
    const int*   pv_ids     = (const int*)  d_in[8];
    const int*   nounk      = (const int*)  d_in[9];
    // d_in[10] = bspn_onehot: unused
    const float* emb        = (const float*)d_in[11];
    const float* attn_W     = (const float*)d_in[12];
    const float* attn_b     = (const float*)d_in[13];
    const float* v_w        = (const float*)d_in[14];
    const float* Wc         = (const float*)d_in[15];
    const float* Wcb        = (const float*)d_in[16];
    const float* Wg         = (const float*)d_in[17];
    const float* Wgb        = (const float*)d_in[18];
    const float* Wih        = (const float*)d_in[19];
    const float* Whh        = (const float*)d_in[20];
    const float* bih        = (const float*)d_in[21];
    const float* bhh        = (const float*)d_in[22];
    float* out = (float*)d_out;

    float* S = nullptr;  cudaGetSymbolAddress((void**)&S, g_scratch);
    __nv_bfloat16* Bf = nullptr;  cudaGetSymbolAddress((void**)&Bf, g_bf);

    float* U    = S + OFF_U;
    float* GH   = S + OFF_GH;
    float* SPU  = S + OFF_SPU;
    float* SPB  = S + OFF_SPB;
    float* SPP  = S + OFF_SPP;
    float* X    = S + OFF_X;
    float* GI   = S + OFF_GI;
    float* HNEW = S + OFF_HNEW;
    float* GEN  = S + OFF_GEN;
    float* CPR  = S + OFF_CPR;

    __nv_bfloat16* bEU  = Bf + BOFF_EU;
    __nv_bfloat16* bEB  = Bf + BOFF_EB;
    __nv_bfloat16* bEP  = Bf + BOFF_EP;
    __nv_bfloat16* bW1  = Bf + BOFF_W1;
    __nv_bfloat16* bW2  = Bf + BOFF_W2;
    __nv_bfloat16* bWC  = Bf + BOFF_WC;
    __nv_bfloat16* bWG  = Bf + BOFF_WG;
    __nv_bfloat16* bWIH = Bf + BOFF_WIH;
    __nv_bfloat16* bWHH = Bf + BOFF_WHH;
    __nv_bfloat16* bH0  = Bf + BOFF_H0;
    __nv_bfloat16* bX   = Bf + BOFF_X;
    __nv_bfloat16* bHN  = Bf + BOFF_HN;
    __nv_bfloat16* bTB  = Bf + BOFF_TBCP;

    // converts
    f2bf_k<<<cdiv(Bn*TU*Hd/4, 256), 256>>>(usdx_h, bEU, Bn*TU*Hd/4);
    f2bf_k<<<cdiv(Bn*TBt*Hd/4, 256), 256>>>(bspn_h, bEB, Bn*TBt*Hd/4);
    f2bf_k<<<cdiv(Bn*TPt*Hd/4, 256), 256>>>(pv_h, bEP, Bn*TPt*Hd/4);
    f2bf_stride_k<<<cdiv(512*512, 256), 256>>>(attn_W, bW1, 512, 512, 2*Hd, 0);
    f2bf_stride_k<<<cdiv(512*512, 256), 256>>>(attn_W, bW2, 512, 512, 2*Hd, Hd);
    f2bf_k<<<cdiv(512*512/4, 256), 256>>>(Wc, bWC, 512*512/4);
    f2bf_k<<<cdiv(3000*512/4, 256), 256>>>(Wg, bWG, 3000*512/4);
    f2bf_k<<<cdiv(1536*2080/4, 256), 256>>>(Wih, bWIH, 1536*2080/4);
    f2bf_k<<<cdiv(1536*512/4, 256), 256>>>(Whh, bWHH, 1536*512/4);
    f2bf_k<<<cdiv(Bn*Hd/4, 256), 256>>>(h0, bH0, Bn*Hd/4);

    // U = h0@W1^T + attn_b ; GH = h0@Whh^T + bhh
    gemm_bf16_k<0><<<dim3(4, 1), 256>>>(bH0, bW1, attn_b, U, nullptr, nullptr, nullptr, nullptr, Bn, 512, 512, 0);
    gemm_bf16_k<0><<<dim3(12, 1), 256>>>(bH0, bWHH, bhh, GH, nullptr, nullptr, nullptr, nullptr, Bn, G3H, 512, 0);

    // attention GEMMs with fused score epilogue (E never materialized)
    gemm_bf16_k<1><<<dim3(4, (Bn*TU)/128), 256>>>(bEU, bW2, nullptr, nullptr, nullptr, SPU, U, v_w, Bn*TU, 512, 512, TU);
    gemm_bf16_k<1><<<dim3(4, (Bn*TBt)/128), 256>>>(bEB, bW2, nullptr, nullptr, nullptr, SPB, U, v_w, Bn*TBt, 512, 512, TBt);
    gemm_bf16_k<1><<<dim3(4, (Bn*TPt)/128), 256>>>(bEP, bW2, nullptr, nullptr, nullptr, SPP, U, v_w, Bn*TPt, 512, 512, TPt);
    // copy GEMM with fused tanh+bias -> bf16
    gemm_bf16_k<2><<<dim3(4, (Bn*TBt)/128), 256>>>(bEB, bWC, Wcb, nullptr, bTB, nullptr, nullptr, nullptr, Bn*TBt, 512, 512, 0);

    // softmax + ctx
    softmax_ctx_k<<<dim3(Bn, 2), 256>>>(SPU, usdx_ids, bEU, X, TU, Ed);
    softmax_ctx_k<<<dim3(Bn, 2), 256>>>(SPB, bspn_ids, bEB, X, TBt, Ed + Hd);
    softmax_ctx_k<<<dim3(Bn, 2), 256>>>(SPP, pv_ids, bEP, X, TPt, Ed + 2*Hd);
    fill_x_k<<<Bn, 256>>>(dec_last_w, emb, db, X);

    // GRU
    f2bf_k<<<cdiv(Bn*XD/4, 256), 256>>>(X, bX, Bn*XD/4);
    gemm_bf16_k<0><<<dim3(12, 1), 256>>>(bX, bWIH, bih, GI, nullptr, nullptr, nullptr, nullptr, Bn, G3H, XD, 0);
    gru_cell_k<<<cdiv(Bn*Hd, 256), 256>>>(GI, GH, h0, HNEW, bHN);

    // heads
    gemm_bf16_k<0><<<dim3(cdiv(3000, 128), 1), 256>>>(bHN, bWG, Wgb, GEN, nullptr, nullptr, nullptr, nullptr, Bn, Vd, 512, 0);
    cpraw_k<<<(Bn*TBt)/8, 256>>>(bTB, HNEW, bspn_ids, CPR);

    final_k<<<Bn, 256>>>(GEN, CPR, nounk, out);
}

// round 4
// speedup vs baseline: 6.2863x; 1.1172x over previous
#include <cuda_runtime.h>
#include <cuda_bf16.h>
#include <math.h>
#include <stdint.h>

// ---------------- problem constants ----------------
#define Bn    128
#define TU    256
#define TBt   128
#define TPt   64
#define Hd    512
#define Ed    512
#define Vd    3000
#define VOOVd 3400
#define PTRd  32
#define XD    2080   // E + 3H + PTR
#define G3H   1536
#define NEGV  (-1e20f)
#define MATT  (Bn*TU + Bn*TBt + Bn*TPt)   // 57344 merged attention rows

// ---------------- fp32 scratch ----------------
constexpr size_t OFF_UGH  = 0;                              // B x 2048 (U | GH)
constexpr size_t OFF_BIAS = OFF_UGH  + (size_t)Bn*2048;     // 2048
constexpr size_t OFF_SPU  = OFF_BIAS + 2048;                // MATT x 4 partial scores
constexpr size_t OFF_SPB  = OFF_SPU  + (size_t)Bn*TU*4;
constexpr size_t OFF_SPP  = OFF_SPB  + (size_t)Bn*TBt*4;
constexpr size_t OFF_X    = OFF_SPP  + (size_t)Bn*TPt*4;    // B x 2080
constexpr size_t OFF_GI   = OFF_X    + (size_t)Bn*XD;       // B x 3H
constexpr size_t OFF_HNEW = OFF_GI   + (size_t)Bn*G3H;
constexpr size_t OFF_GEN  = OFF_HNEW + (size_t)Bn*Hd;       // B x V
constexpr size_t OFF_CPR  = OFF_GEN  + (size_t)Bn*Vd;
constexpr size_t TOT_F32  = OFF_CPR  + (size_t)Bn*TBt;
__device__ float g_scratch[TOT_F32];

// ---------------- bf16 scratch (EU/EB/EP contiguous; W1 then WHH contiguous) ----------------
constexpr size_t BOFF_EU   = 0;
constexpr size_t BOFF_EB   = BOFF_EU  + (size_t)Bn*TU*Hd;
constexpr size_t BOFF_EP   = BOFF_EB  + (size_t)Bn*TBt*Hd;
constexpr size_t BOFF_W1   = BOFF_EP  + (size_t)Bn*TPt*Hd;   // 512x512
constexpr size_t BOFF_WHH  = BOFF_W1  + (size_t)512*512;     // 1536x512 (contiguous after W1)
constexpr size_t BOFF_W2   = BOFF_WHH + (size_t)1536*512;
constexpr size_t BOFF_WC   = BOFF_W2  + (size_t)512*512;
constexpr size_t BOFF_WG   = BOFF_WC  + (size_t)512*512;     // 3000x512
constexpr size_t BOFF_WIH  = BOFF_WG  + (size_t)3000*512;    // 1536x2080
constexpr size_t BOFF_H0   = BOFF_WIH + (size_t)1536*2080;   // 128x512
constexpr size_t BOFF_X    = BOFF_H0  + (size_t)Bn*Hd;       // 128x2080
constexpr size_t BOFF_HN   = BOFF_X   + (size_t)Bn*XD;       // 128x512
constexpr size_t BOFF_TBCP = BOFF_HN  + (size_t)Bn*Hd;       // 16384x512 tanh(copy)
constexpr size_t TOT_BF    = BOFF_TBCP+ (size_t)Bn*TBt*Hd;
__device__ __nv_bfloat16 g_bf[TOT_BF];

__device__ __forceinline__ float sigmoidf_(float x) { return 1.0f / (1.0f + expf(-x)); }

// ---------------- merged converts ----------------
__global__ void conv_enc_k(const float* __restrict__ eu, const float* __restrict__ eb,
                           const float* __restrict__ ep, __nv_bfloat16* __restrict__ bf) {
    int i = blockIdx.x * 256 + threadIdx.x;   // float4 index
    float4 v; __nv_bfloat16* d;
    if (i < 4194304)      { v = ((const float4*)eu)[i]; d = bf + BOFF_EU + (size_t)i * 4; }
    else if (i < 6291456) { int j = i - 4194304; v = ((const float4*)eb)[j]; d = bf + BOFF_EB + (size_t)j * 4; }
    else if (i < 7340032) { int j = i - 6291456; v = ((const float4*)ep)[j]; d = bf + BOFF_EP + (size_t)j * 4; }
    else return;
    ((__nv_bfloat162*)d)[0] = __floats2bfloat162_rn(v.x, v.y);
    ((__nv_bfloat162*)d)[1] = __floats2bfloat162_rn(v.z, v.w);
}

__global__ void conv_weights_k(const float* __restrict__ aw, const float* __restrict__ wc,
                               const float* __restrict__ wg, const float* __restrict__ wih,
                               const float* __restrict__ whh, const float* __restrict__ h0,
                               __nv_bfloat16* __restrict__ bf) {
    int i = blockIdx.x * 256 + threadIdx.x;
    if (i < 262144)       { int r = i >> 9, c = i & 511; bf[BOFF_W1 + i] = __float2bfloat16(aw[(size_t)r * 1024 + c]); }
    else if (i < 524288)  { int j = i - 262144; int r = j >> 9, c = j & 511; bf[BOFF_W2 + j] = __float2bfloat16(aw[(size_t)r * 1024 + 512 + c]); }
    else if (i < 786432)  { int j = i - 524288;  bf[BOFF_WC  + j] = __float2bfloat16(wc[j]); }
    else if (i < 2322432) { int j = i - 786432;  bf[BOFF_WG  + j] = __float2bfloat16(wg[j]); }
    else if (i < 5517312) { int j = i - 2322432; bf[BOFF_WIH + j] = __float2bfloat16(wih[j]); }
    else if (i < 6303744) { int j = i - 5517312; bf[BOFF_WHH + j] = __float2bfloat16(whh[j]); }
    else if (i < 6369280) { int j = i - 6303744; bf[BOFF_H0  + j] = __float2bfloat16(h0[j]); }
}

__global__ void bias_cat_k(const float* __restrict__ ab, const float* __restrict__ bhh,
                           float* __restrict__ bias) {
    int i = blockIdx.x * 256 + threadIdx.x;
    if (i < 512) bias[i] = ab[i];
    else if (i < 2048) bias[i] = bhh[i - 512];
}

__global__ void f2bf_k(const float* __restrict__ in, __nv_bfloat16* __restrict__ outp, int n4) {
    int i = blockIdx.x * 256 + threadIdx.x;
    if (i >= n4) return;
    float4 v = ((const float4*)in)[i];
    ((__nv_bfloat162*)outp)[2*i]   = __floats2bfloat162_rn(v.x, v.y);
    ((__nv_bfloat162*)outp)[2*i+1] = __floats2bfloat162_rn(v.z, v.w);
}

// ---------------- mma helpers ----------------
__device__ __forceinline__ uint32_t sptr(const void* p) {
    return (uint32_t)__cvta_generic_to_shared(p);
}
__device__ __forceinline__ void ldsm_x4(uint32_t& r0, uint32_t& r1, uint32_t& r2, uint32_t& r3, uint32_t a) {
    asm volatile("ldmatrix.sync.aligned.m8n8.x4.shared.b16 {%0,%1,%2,%3}, [%4];\n"
                 : "=r"(r0), "=r"(r1), "=r"(r2), "=r"(r3) : "r"(a));
}
__device__ __forceinline__ void mma_bf16(float* d, const uint32_t* a, const uint32_t* b) {
    asm volatile("mma.sync.aligned.m16n8k16.row.col.f32.bf16.bf16.f32 "
                 "{%0,%1,%2,%3},{%4,%5,%6,%7},{%8,%9},{%0,%1,%2,%3};\n"
                 : "+f"(d[0]), "+f"(d[1]), "+f"(d[2]), "+f"(d[3])
                 : "r"(a[0]), "r"(a[1]), "r"(a[2]), "r"(a[3]), "r"(b[0]), "r"(b[1]));
}
__device__ __forceinline__ void cp16(uint32_t dst, const void* src, bool pred) {
    int sz = pred ? 16 : 0;
    asm volatile("cp.async.cg.shared.global [%0], [%1], 16, %2;\n"
                 :: "r"(dst), "l"(src), "r"(sz));
}
__device__ __forceinline__ void cp_commit() { asm volatile("cp.async.commit_group;\n"); }
template<int Nw> __device__ __forceinline__ void cp_wait() {
    asm volatile("cp.async.wait_group %0;\n" :: "n"(Nw));
}

#define GPAD 40   // smem row stride (bf16)
#define STG  3    // pipeline stages
constexpr int DSMEM = STG * 2 * 128 * GPAD * 2;   // 61440 bytes

// batch index for merged attention rows
__device__ __forceinline__ int bat_of(int r) {
    return (r < Bn*TU) ? (r >> 8)
         : (r < Bn*TU + Bn*TBt) ? ((r - Bn*TU) >> 7)
         : ((r - Bn*TU - Bn*TBt) >> 6);
}

// MODE 0: C = A@W^T + bias (fp32, row stride N)
// MODE 1: merged attention score partials: spart[r*4+bx] = sum_cols v[c]*tanh(acc+u[b,c])
// MODE 2: Ct = bf16(tanh(acc + bias))
template<int MODE>
__global__ __launch_bounds__(256) void gemm_bf16_k(
    const __nv_bfloat16* __restrict__ A, const __nv_bfloat16* __restrict__ Bw,
    const float* __restrict__ bias, float* __restrict__ C,
    __nv_bfloat16* __restrict__ Ct, float* __restrict__ spart,
    const float* __restrict__ u, const float* __restrict__ v,
    int M, int N, int K, int ustride)
{
    extern __shared__ __align__(16) __nv_bfloat16 dsm[];
    __nv_bfloat16* As = dsm;                         // [STG][128*GPAD]
    __nv_bfloat16* Bs = dsm + (size_t)STG * 128 * GPAD;
    __shared__ float part[128][4];
    int tid = threadIdx.x;
    int warp = tid >> 5, lane = tid & 31;
    int m0 = blockIdx.y * 128, n0 = blockIdx.x * 128;
    int wm = (warp >> 2) * 64, wn = (warp & 3) * 32;

    float acc[4][4][4];
    #pragma unroll
    for (int i = 0; i < 4; i++)
        #pragma unroll
        for (int j = 0; j < 4; j++)
            #pragma unroll
            for (int q = 0; q < 4; q++) acc[i][j][q] = 0.f;

    int lr = tid >> 1;                 // 0..127
    int lc0 = (tid & 1) * 16;          // 0 or 16
    auto load_stage = [&](int st, int k0) {
        __nv_bfloat16* as = As + (size_t)st * 128 * GPAD;
        __nv_bfloat16* bs = Bs + (size_t)st * 128 * GPAD;
        #pragma unroll
        for (int s = 0; s < 2; s++) {
            int c = lc0 + s * 8;
            cp16(sptr(as + lr * GPAD + c), A + (size_t)(m0 + lr) * K + k0 + c, true);
            int gn = n0 + lr;
            bool pred = gn < N;
            cp16(sptr(bs + lr * GPAD + c),
                 Bw + (size_t)(pred ? gn : (N - 1)) * K + k0 + c, pred);
        }
        cp_commit();
    };

    int nk = K >> 5;
    load_stage(0, 0);
    load_stage(1, 32);
    for (int it = 0; it < nk; it++) {
        if (it == nk - 1) cp_wait<0>(); else cp_wait<1>();
        __syncthreads();
        if (it + 2 < nk) load_stage((it + 2) % STG, (it + 2) * 32);
        int cur = it % STG;
        __nv_bfloat16* as = As + (size_t)cur * 128 * GPAD;
        __nv_bfloat16* bs = Bs + (size_t)cur * 128 * GPAD;
        #pragma unroll
        for (int kk = 0; kk < 2; kk++) {
            int kb = kk * 16;
            uint32_t afr[4][4], bfr[4][2];
            #pragma unroll
            for (int mt = 0; mt < 4; mt++) {
                int row = wm + mt * 16 + (lane & 15);
                int col = kb + (lane >> 4) * 8;
                ldsm_x4(afr[mt][0], afr[mt][1], afr[mt][2], afr[mt][3],
                        sptr(as + row * GPAD + col));
            }
            #pragma unroll
            for (int p = 0; p < 2; p++) {
                int row = wn + p * 16 + (lane & 7) + ((lane >> 4) & 1) * 8;
                int col = kb + ((lane >> 3) & 1) * 8;
                ldsm_x4(bfr[2*p][0], bfr[2*p][1], bfr[2*p+1][0], bfr[2*p+1][1],
                        sptr(bs + row * GPAD + col));
            }
            #pragma unroll
            for (int mt = 0; mt < 4; mt++)
                #pragma unroll
                for (int nt = 0; nt < 4; nt++)
                    mma_bf16(acc[mt][nt], afr[mt], bfr[nt]);
        }
    }

    if (MODE == 0) {
        #pragma unroll
        for (int mt = 0; mt < 4; mt++) {
            int r = m0 + wm + mt * 16 + (lane >> 2);
            #pragma unroll
            for (int nt = 0; nt < 4; nt++) {
                int col = n0 + wn + nt * 8 + (lane & 3) * 2;
                if (col < N) {
                    float b0 = bias ? bias[col] : 0.f;
                    float b1 = bias ? bias[col + 1] : 0.f;
                    *(float2*)(C + (size_t)r * N + col) =
                        make_float2(acc[mt][nt][0] + b0, acc[mt][nt][1] + b1);
                    *(float2*)(C + (size_t)(r + 8) * N + col) =
                        make_float2(acc[mt][nt][2] + b0, acc[mt][nt][3] + b1);
                }
            }
        }
    } else if (MODE == 2) {
        #pragma unroll
        for (int mt = 0; mt < 4; mt++) {
            int r = m0 + wm + mt * 16 + (lane >> 2);
            #pragma unroll
            for (int nt = 0; nt < 4; nt++) {
                int col = n0 + wn + nt * 8 + (lane & 3) * 2;
                float b0 = bias[col], b1 = bias[col + 1];
                *(__nv_bfloat162*)(Ct + (size_t)r * N + col) =
                    __floats2bfloat162_rn(tanhf(acc[mt][nt][0] + b0), tanhf(acc[mt][nt][1] + b1));
                *(__nv_bfloat162*)(Ct + (size_t)(r + 8) * N + col) =
                    __floats2bfloat162_rn(tanhf(acc[mt][nt][2] + b0), tanhf(acc[mt][nt][3] + b1));
            }
        }
    } else {  // MODE 1
        #pragma unroll
        for (int mt = 0; mt < 4; mt++) {
            int r0 = wm + mt * 16 + (lane >> 2);
            int r1 = r0 + 8;
            const float* u0 = u + (size_t)bat_of(m0 + r0) * ustride;
            const float* u1 = u + (size_t)bat_of(m0 + r1) * ustride;
            float ls0 = 0.f, ls1 = 0.f;
            #pragma unroll
            for (int nt = 0; nt < 4; nt++) {
                int col = n0 + wn + nt * 8 + (lane & 3) * 2;
                #pragma unroll
                for (int q = 0; q < 2; q++) {
                    float vv = v[col + q];
                    ls0 += vv * tanhf(acc[mt][nt][q]     + u0[col + q]);
                    ls1 += vv * tanhf(acc[mt][nt][2 + q] + u1[col + q]);
                }
            }
            #pragma unroll
            for (int s = 1; s < 4; s <<= 1) {
                ls0 += __shfl_xor_sync(0xffffffffu, ls0, s);
                ls1 += __shfl_xor_sync(0xffffffffu, ls1, s);
            }
            if ((lane & 3) == 0) {
                part[r0][warp & 3] = ls0;
                part[r1][warp & 3] = ls1;
            }
        }
        __syncthreads();
        if (tid < 128) {
            float tot = part[tid][0] + part[tid][1] + part[tid][2] + part[tid][3];
            spart[(size_t)(m0 + tid) * 4 + blockIdx.x] = tot;
        }
    }
}

// ---------------- score-sum + mask + softmax + ctx (bf16 enc) ----------------
__global__ void softmax_ctx_k(const float* __restrict__ spart, const int* __restrict__ ids,
                              const __nv_bfloat16* __restrict__ enc,
                              float* __restrict__ x, int T, int xoff) {
    int b = blockIdx.x, chunk = blockIdx.y, tid = threadIdx.x;
    __shared__ float sw[256];
    __shared__ float red[256];
    float sv = -3.0e38f;
    if (tid < T) {
        const float* sp = spart + (size_t)(b * T + tid) * 4;
        sv = sp[0] + sp[1] + sp[2] + sp[3];
        if (ids[(size_t)b * T + tid] == 0) sv = NEGV;
    }
    red[tid] = sv; __syncthreads();
    for (int s = 128; s; s >>= 1) { if (tid < s) red[tid] = fmaxf(red[tid], red[tid + s]); __syncthreads(); }
    float m = red[0]; __syncthreads();
    float e = (tid < T) ? expf(sv - m) : 0.f;
    red[tid] = e; __syncthreads();
    for (int s = 128; s; s >>= 1) { if (tid < s) red[tid] += red[tid + s]; __syncthreads(); }
    float Z = red[0]; __syncthreads();
    sw[tid] = e / Z; __syncthreads();
    int h = chunk * 256 + tid;
    float acc = 0.f;
    const __nv_bfloat16* ep = enc + (size_t)b * T * Hd + h;
    #pragma unroll 4
    for (int t = 0; t < T; t++) acc += sw[t] * __bfloat162float(ep[(size_t)t * Hd]);
    x[(size_t)b * XD + xoff + h] = acc;
}

// ---------------- x: emb + db slots ----------------
__global__ void fill_x_k(const int* __restrict__ w, const float* __restrict__ emb_table,
                         const float* __restrict__ db, float* __restrict__ x) {
    int b = blockIdx.x, tid = threadIdx.x;
    int wid = w[b];
    for (int i = tid; i < Ed; i += 256) x[(size_t)b * XD + i] = emb_table[(size_t)wid * Ed + i];
    for (int i = tid; i < PTRd; i += 256) x[(size_t)b * XD + Ed + 3 * Hd + i] = db[(size_t)b * PTRd + i];
}

// ---------------- GRU cell (gh has row stride ghs) ----------------
__global__ void gru_cell_k(const float* __restrict__ gi, const float* __restrict__ gh, int ghs,
                           const float* __restrict__ h0, float* __restrict__ hnew,
                           __nv_bfloat16* __restrict__ hnbf) {
    int i = blockIdx.x * 256 + threadIdx.x;
    if (i >= Bn * Hd) return;
    int b = i / Hd, j = i % Hd;
    const float* gib = gi + (size_t)b * G3H;
    const float* ghb = gh + (size_t)b * ghs;
    float r = sigmoidf_(gib[j] + ghb[j]);
    float z = sigmoidf_(gib[Hd + j] + ghb[Hd + j]);
    float n = tanhf(gib[2 * Hd + j] + r * ghb[2 * Hd + j]);
    float hv = (1.f - z) * n + z * h0[i];
    hnew[i] = hv;
    hnbf[i] = __float2bfloat16(hv);
}

// ---------------- cp_raw: dot(hnew, tanhBCP) ----------------
__global__ void cpraw_k(const __nv_bfloat16* __restrict__ TB, const float* __restrict__ hnew,
                        const int* __restrict__ ids, float* __restrict__ cpr) {
    int tok = blockIdx.x * 8 + (threadIdx.x >> 5);
    int lane = threadIdx.x & 31;
    int b = tok / TBt;
    const __nv_bfloat162* e2 = (const __nv_bfloat162*)(TB + (size_t)tok * Hd);
    const float2* hn2 = (const float2*)(hnew + (size_t)b * Hd);
    float acc = 0.f;
    #pragma unroll 4
    for (int j = lane; j < Hd / 2; j += 32) {
        __nv_bfloat162 p = e2[j];
        float2 h2 = hn2[j];
        acc += h2.x * __bfloat162float(p.x) + h2.y * __bfloat162float(p.y);
    }
    #pragma unroll
    for (int s = 16; s; s >>= 1) acc += __shfl_down_sync(0xffffffffu, acc, s);
    if (lane == 0) cpr[tok] = (ids[tok] == 0) ? NEGV : acc;
}

// ---------------- final epilogue ----------------
__global__ void final_k(const float* __restrict__ gen, const float* __restrict__ cpr,
                        const int* __restrict__ nounk, float* __restrict__ out) {
    int b = blockIdx.x, tid = threadIdx.x;
    __shared__ float Lg[Vd];
    __shared__ float Lc[Vd + TBt];
    __shared__ float addv[VOOVd - Vd];
    __shared__ float red[256];
    for (int n = tid; n < Vd; n += 256) Lg[n] = gen[(size_t)b * Vd + n];
    for (int n = tid; n < Vd + TBt; n += 256) Lc[n] = 0.f;
    for (int n = tid; n < VOOVd - Vd; n += 256) addv[n] = 0.f;
    __syncthreads();
    if (tid == 0) {
        for (int t = 0; t < TBt; t++) {
            int nk = nounk[(size_t)b * TBt + t];
            int col = (nk < Vd) ? nk : (Vd + t);
            Lc[col] += cpr[(size_t)b * TBt + t];
        }
    }
    __syncthreads();
    float lm = -3.0e38f;
    for (int n = tid; n < 2 * Vd + TBt; n += 256) {
        float v = (n < Vd) ? Lg[n] : Lc[n - Vd];
        lm = fmaxf(lm, v);
    }
    red[tid] = lm; __syncthreads();
    for (int s = 128; s; s >>= 1) { if (tid < s) red[tid] = fmaxf(red[tid], red[tid + s]); __syncthreads(); }
    float M = red[0]; __syncthreads();
    float ls = 0.f;
    for (int n = tid; n < 2 * Vd + TBt; n += 256) {
        float v = (n < Vd) ? Lg[n] : Lc[n - Vd];
        ls += expf(v - M);
    }
    red[tid] = ls; __syncthreads();
    for (int s = 128; s; s >>= 1) { if (tid < s) red[tid] += red[tid + s]; __syncthreads(); }
    float logZ = M + logf(red[0]); __syncthreads();
    if (tid == 0) {
        for (int t = 0; t < TBt; t++) {
            int nk = nounk[(size_t)b * TBt + t];
            if (nk >= Vd) addv[nk - Vd] += expf(Lc[Vd + t] - logZ);
        }
    }
    __syncthreads();
    for (int n = tid; n < VOOVd; n += 256) {
        float val;
        if (n < Vd) {
            float a = Lg[n] - logZ;
            float c = Lc[n] - logZ;
            float mm = fmaxf(a, c);
            val = mm + log1pf(expf(-fabsf(a - c)));
        } else {
            float v = addv[n - Vd];
            val = (v > 0.f) ? logf(fmaxf(v, 1e-38f)) : NEGV;
        }
        out[(size_t)b * VOOVd + n] = val;
    }
}

// ---------------- host ----------------
static inline int cdiv(int a, int b) { return (a + b - 1) / b; }

extern "C" void kernel_launch(void* const* d_in, const int* in_sizes, int n_in,
                              void* d_out, int out_size) {
    const int*   dec_last_w = (const int*)  d_in[0];
    const float* h0         = (const float*)d_in[1];
    const float* usdx_h     = (const float*)d_in[2];
    const float* bspn_h     = (const float*)d_in[3];
    const float* pv_h       = (const float*)d_in[4];
    const float* db         = (const float*)d_in[5];
    const int*   usdx_ids   = (const int*)  d_in[6];
    const int*   bspn_ids   = (const int*)  d_in[7];
    const int*   pv_ids     = (const int*)  d_in[8];
    const int*   nounk      = (const int*)  d_in[9];
    // d_in[10] = bspn_onehot: unused
    const float* emb        = (const float*)d_in[11];
    const float* attn_W     = (const float*)d_in[12];
    const float* attn_b     = (const float*)d_in[13];
    const float* v_w        = (const float*)d_in[14];
    const float* Wc         = (const float*)d_in[15];
    const float* Wcb        = (const float*)d_in[16];
    const float* Wg         = (const float*)d_in[17];
    const float* Wgb        = (const float*)d_in[18];
    const float* Wih        = (const float*)d_in[19];
    const float* Whh        = (const float*)d_in[20];
    const float* bih        = (const float*)d_in[21];
    const float* bhh        = (const float*)d_in[22];
    float* out = (float*)d_out;

    float* S = nullptr;  cudaGetSymbolAddress((void**)&S, g_scratch);
    __nv_bfloat16* Bf = nullptr;  cudaGetSymbolAddress((void**)&Bf, g_bf);

    float* UGH  = S + OFF_UGH;     // U = cols[0:512), GH = cols[512:2048), stride 2048
    float* BIAS = S + OFF_BIAS;
    float* SPU  = S + OFF_SPU;
    float* SPB  = S + OFF_SPB;
    float* SPP  = S + OFF_SPP;
    float* X    = S + OFF_X;
    float* GI   = S + OFF_GI;
    float* HNEW = S + OFF_HNEW;
    float* GEN  = S + OFF_GEN;
    float* CPR  = S + OFF_CPR;

    __nv_bfloat16* bEU  = Bf + BOFF_EU;   // merged attention A base
    __nv_bfloat16* bEB  = Bf + BOFF_EB;
    __nv_bfloat16* bEP  = Bf + BOFF_EP;
    __nv_bfloat16* bW1c = Bf + BOFF_W1;   // W1 (512) ++ WHH (1536) = 2048 rows
    __nv_bfloat16* bW2  = Bf + BOFF_W2;
    __nv_bfloat16* bWC  = Bf + BOFF_WC;
    __nv_bfloat16* bWG  = Bf + BOFF_WG;
    __nv_bfloat16* bWIH = Bf + BOFF_WIH;
    __nv_bfloat16* bH0  = Bf + BOFF_H0;
    __nv_bfloat16* bX   = Bf + BOFF_X;
    __nv_bfloat16* bHN  = Bf + BOFF_HN;
    __nv_bfloat16* bTB  = Bf + BOFF_TBCP;

    static bool attr_set = false;
    if (!attr_set) {
        cudaFuncSetAttribute(gemm_bf16_k<0>, cudaFuncAttributeMaxDynamicSharedMemorySize, DSMEM);
        cudaFuncSetAttribute(gemm_bf16_k<1>, cudaFuncAttributeMaxDynamicSharedMemorySize, DSMEM);
        cudaFuncSetAttribute(gemm_bf16_k<2>, cudaFuncAttributeMaxDynamicSharedMemorySize, DSMEM);
        attr_set = true;
    }

    // launch 0-4: converts + prep + first GEMMs
    conv_enc_k<<<28672, 256>>>(usdx_h, bspn_h, pv_h, Bf);
    conv_weights_k<<<cdiv(6369280, 256), 256>>>(attn_W, Wc, Wg, Wih, Whh, h0, Bf);
    bias_cat_k<<<8, 256>>>(attn_b, bhh, BIAS);
    // UGH = h0 @ [W1;Whh]^T + [attn_b;bhh]   (U | GH)
    gemm_bf16_k<0><<<dim3(16, 1), 256, DSMEM>>>(bH0, bW1c, BIAS, UGH, nullptr, nullptr, nullptr, nullptr, Bn, 2048, 512, 0);
    // copy GEMM: tanh(bspn@Wc^T + Wcb) -> bf16
    gemm_bf16_k<2><<<dim3(4, (Bn*TBt)/128), 256, DSMEM>>>(bEB, bWC, Wcb, nullptr, bTB, nullptr, nullptr, nullptr, Bn*TBt, 512, 512, 0);
    // launch 5: merged attention score GEMM (ncu target)
    gemm_bf16_k<1><<<dim3(4, MATT/128), 256, DSMEM>>>(bEU, bW2, nullptr, nullptr, nullptr, SPU, UGH, v_w, MATT, 512, 512, 2048);

    // softmax + ctx
    softmax_ctx_k<<<dim3(Bn, 2), 256>>>(SPU, usdx_ids, bEU, X, TU, Ed);
    softmax_ctx_k<<<dim3(Bn, 2), 256>>>(SPB, bspn_ids, bEB, X, TBt, Ed + Hd);
    softmax_ctx_k<<<dim3(Bn, 2), 256>>>(SPP, pv_ids, bEP, X, TPt, Ed + 2*Hd);
    fill_x_k<<<Bn, 256>>>(dec_last_w, emb, db, X);

    // GRU
    f2bf_k<<<cdiv(Bn*XD/4, 256), 256>>>(X, bX, Bn*XD/4);
    gemm_bf16_k<0><<<dim3(12, 1), 256, DSMEM>>>(bX, bWIH, bih, GI, nullptr, nullptr, nullptr, nullptr, Bn, G3H, XD, 0);
    gru_cell_k<<<cdiv(Bn*Hd, 256), 256>>>(GI, UGH + 512, 2048, h0, HNEW, bHN);

    // heads
    gemm_bf16_k<0><<<dim3(cdiv(3000, 128), 1), 256, DSMEM>>>(bHN, bWG, Wgb, GEN, nullptr, nullptr, nullptr, nullptr, Bn, Vd, 512, 0);
    cpraw_k<<<(Bn*TBt)/8, 256>>>(bTB, HNEW, bspn_ids, CPR);

    final_k<<<Bn, 256>>>(GEN, CPR, nounk, out);
}

// round 5
// speedup vs baseline: 7.3930x; 1.1761x over previous
#include <cuda_runtime.h>
#include <cuda_bf16.h>
#include <math.h>
#include <stdint.h>

// ---------------- problem constants ----------------
#define Bn    128
#define TU    256
#define TBt   128
#define TPt   64
#define Hd    512
#define Ed    512
#define Vd    3000
#define VOOVd 3400
#define PTRd  32
#define XD    2080
#define G3H   1536
#define NEGV  (-1e20f)
#define MATT  (Bn*TU + Bn*TBt + Bn*TPt)   // 57344 merged attention rows
#define USLAB (Bn*2048)                    // UGH partial slab stride (floats)

// ---------------- fp32 scratch ----------------
constexpr size_t OFF_UGHP = 0;                               // 4 x (B x 2048)
constexpr size_t OFF_GIP  = OFF_UGHP + (size_t)4*Bn*2048;    // 5 x (B x 1536)
constexpr size_t OFF_GENP = OFF_GIP  + (size_t)5*Bn*G3H;     // 4 x (B x 3000)
constexpr size_t OFF_SP   = OFF_GENP + (size_t)4*Bn*Vd;      // MATT x 2 score partials
constexpr size_t OFF_X    = OFF_SP   + (size_t)MATT*2;       // B x 2080
constexpr size_t OFF_HNEW = OFF_X    + (size_t)Bn*XD;
constexpr size_t OFF_CPR  = OFF_HNEW + (size_t)Bn*Hd;
constexpr size_t TOT_F32  = OFF_CPR  + (size_t)Bn*TBt;
__device__ float g_scratch[TOT_F32];

// ---------------- bf16 scratch ----------------
constexpr size_t BOFF_EU   = 0;
constexpr size_t BOFF_EB   = BOFF_EU  + (size_t)Bn*TU*Hd;
constexpr size_t BOFF_EP   = BOFF_EB  + (size_t)Bn*TBt*Hd;
constexpr size_t BOFF_W1   = BOFF_EP  + (size_t)Bn*TPt*Hd;   // 512x512
constexpr size_t BOFF_WHH  = BOFF_W1  + (size_t)512*512;     // 1536x512 (contiguous after W1)
constexpr size_t BOFF_W2   = BOFF_WHH + (size_t)1536*512;
constexpr size_t BOFF_WC   = BOFF_W2  + (size_t)512*512;
constexpr size_t BOFF_WG   = BOFF_WC  + (size_t)512*512;     // 3000x512
constexpr size_t BOFF_WIH  = BOFF_WG  + (size_t)3000*512;    // 1536x2080
constexpr size_t BOFF_H0   = BOFF_WIH + (size_t)1536*2080;   // 128x512
constexpr size_t BOFF_X    = BOFF_H0  + (size_t)Bn*Hd;       // 128x2080
constexpr size_t BOFF_HN   = BOFF_X   + (size_t)Bn*XD;       // 128x512
constexpr size_t BOFF_TBCP = BOFF_HN  + (size_t)Bn*Hd;       // 16384x512 tanh(copy)
constexpr size_t TOT_BF    = BOFF_TBCP+ (size_t)Bn*TBt*Hd;
__device__ __nv_bfloat16 g_bf[TOT_BF];

__device__ __forceinline__ float sigmoidf_(float x) { return 1.0f / (1.0f + expf(-x)); }

// ---------------- converts ----------------
__global__ void conv_enc_k(const float* __restrict__ eu, const float* __restrict__ eb,
                           const float* __restrict__ ep, __nv_bfloat16* __restrict__ bf) {
    int i = blockIdx.x * 256 + threadIdx.x;
    float4 v; __nv_bfloat16* d;
    if (i < 4194304)      { v = ((const float4*)eu)[i]; d = bf + BOFF_EU + (size_t)i * 4; }
    else if (i < 6291456) { int j = i - 4194304; v = ((const float4*)eb)[j]; d = bf + BOFF_EB + (size_t)j * 4; }
    else if (i < 7340032) { int j = i - 6291456; v = ((const float4*)ep)[j]; d = bf + BOFF_EP + (size_t)j * 4; }
    else return;
    ((__nv_bfloat162*)d)[0] = __floats2bfloat162_rn(v.x, v.y);
    ((__nv_bfloat162*)d)[1] = __floats2bfloat162_rn(v.z, v.w);
}

__global__ void conv_weights_k(const float* __restrict__ aw, const float* __restrict__ wc,
                               const float* __restrict__ wg, const float* __restrict__ wih,
                               const float* __restrict__ whh, const float* __restrict__ h0,
                               __nv_bfloat16* __restrict__ bf) {
    int i = blockIdx.x * 256 + threadIdx.x;
    if (i < 262144)       { int r = i >> 9, c = i & 511; bf[BOFF_W1 + i] = __float2bfloat16(aw[(size_t)r * 1024 + c]); }
    else if (i < 524288)  { int j = i - 262144; int r = j >> 9, c = j & 511; bf[BOFF_W2 + j] = __float2bfloat16(aw[(size_t)r * 1024 + 512 + c]); }
    else if (i < 786432)  { int j = i - 524288;  bf[BOFF_WC  + j] = __float2bfloat16(wc[j]); }
    else if (i < 2322432) { int j = i - 786432;  bf[BOFF_WG  + j] = __float2bfloat16(wg[j]); }
    else if (i < 5517312) { int j = i - 2322432; bf[BOFF_WIH + j] = __float2bfloat16(wih[j]); }
    else if (i < 6303744) { int j = i - 5517312; bf[BOFF_WHH + j] = __float2bfloat16(whh[j]); }
    else if (i < 6369280) { int j = i - 6303744; bf[BOFF_H0  + j] = __float2bfloat16(h0[j]); }
}

__global__ void f2bf_k(const float* __restrict__ in, __nv_bfloat16* __restrict__ outp, int n4) {
    int i = blockIdx.x * 256 + threadIdx.x;
    if (i >= n4) return;
    float4 v = ((const float4*)in)[i];
    ((__nv_bfloat162*)outp)[2*i]   = __floats2bfloat162_rn(v.x, v.y);
    ((__nv_bfloat162*)outp)[2*i+1] = __floats2bfloat162_rn(v.z, v.w);
}

// ---------------- mma helpers ----------------
__device__ __forceinline__ uint32_t sptr(const void* p) {
    return (uint32_t)__cvta_generic_to_shared(p);
}
__device__ __forceinline__ void ldsm_x4(uint32_t& r0, uint32_t& r1, uint32_t& r2, uint32_t& r3, uint32_t a) {
    asm volatile("ldmatrix.sync.aligned.m8n8.x4.shared.b16 {%0,%1,%2,%3}, [%4];\n"
                 : "=r"(r0), "=r"(r1), "=r"(r2), "=r"(r3) : "r"(a));
}
__device__ __forceinline__ void mma_bf16(float* d, const uint32_t* a, const uint32_t* b) {
    asm volatile("mma.sync.aligned.m16n8k16.row.col.f32.bf16.bf16.f32 "
                 "{%0,%1,%2,%3},{%4,%5,%6,%7},{%8,%9},{%0,%1,%2,%3};\n"
                 : "+f"(d[0]), "+f"(d[1]), "+f"(d[2]), "+f"(d[3])
                 : "r"(a[0]), "r"(a[1]), "r"(a[2]), "r"(a[3]), "r"(b[0]), "r"(b[1]));
}
__device__ __forceinline__ void cp16(uint32_t dst, const void* src, bool pred) {
    int sz = pred ? 16 : 0;
    asm volatile("cp.async.cg.shared.global [%0], [%1], 16, %2;\n"
                 :: "r"(dst), "l"(src), "r"(sz));
}
__device__ __forceinline__ void cp_commit() { asm volatile("cp.async.commit_group;\n"); }
template<int Nw> __device__ __forceinline__ void cp_wait() {
    asm volatile("cp.async.wait_group %0;\n" :: "n"(Nw));
}

#define GPAD 40
#define STG  3
constexpr int DSMEM_SK  = STG * 2 * 128 * GPAD * 2;           // 61440
constexpr int DSMEM_BIG = STG * (128 + 256) * GPAD * 2;       // 92160

__device__ __forceinline__ int bat_of(int r) {
    return (r < Bn*TU) ? (r >> 8)
         : (r < Bn*TU + Bn*TBt) ? ((r - Bn*TU) >> 7)
         : ((r - Bn*TU - Bn*TBt) >> 6);
}

// ---------------- skinny split-K GEMM: Cp[z] = A[:,z*Kc:(z+1)*Kc] @ W[:, same]^T ----------------
__global__ __launch_bounds__(256) void skinny_gemm_k(
    const __nv_bfloat16* __restrict__ A, int lda,
    const __nv_bfloat16* __restrict__ Bw, int ldb,
    float* __restrict__ Cp, int M, int N, int Kc)
{
    extern __shared__ __align__(16) __nv_bfloat16 dsm[];
    __nv_bfloat16* As = dsm;
    __nv_bfloat16* Bs = dsm + (size_t)STG * 128 * GPAD;
    int tid = threadIdx.x;
    int warp = tid >> 5, lane = tid & 31;
    int m0 = blockIdx.y * 128, n0 = blockIdx.x * 128;
    int koff = blockIdx.z * Kc;
    float* C = Cp + (size_t)blockIdx.z * M * N;
    int wm = (warp >> 2) * 64, wn = (warp & 3) * 32;

    float acc[4][4][4];
    #pragma unroll
    for (int i = 0; i < 4; i++)
        #pragma unroll
        for (int j = 0; j < 4; j++)
            #pragma unroll
            for (int q = 0; q < 4; q++) acc[i][j][q] = 0.f;

    int lr = tid >> 1;
    int lc0 = (tid & 1) * 16;
    auto load_stage = [&](int st, int k0) {
        __nv_bfloat16* as = As + (size_t)st * 128 * GPAD;
        __nv_bfloat16* bs = Bs + (size_t)st * 128 * GPAD;
        #pragma unroll
        for (int s = 0; s < 2; s++) {
            int c = lc0 + s * 8;
            cp16(sptr(as + lr * GPAD + c), A + (size_t)(m0 + lr) * lda + koff + k0 + c, true);
            int gn = n0 + lr;
            bool pred = gn < N;
            cp16(sptr(bs + lr * GPAD + c),
                 Bw + (size_t)(pred ? gn : (N - 1)) * ldb + koff + k0 + c, pred);
        }
        cp_commit();
    };

    int nk = Kc >> 5;
    load_stage(0, 0);
    load_stage(1, 32);
    for (int it = 0; it < nk; it++) {
        if (it == nk - 1) cp_wait<0>(); else cp_wait<1>();
        __syncthreads();
        if (it + 2 < nk) load_stage((it + 2) % STG, (it + 2) * 32);
        int cur = it % STG;
        __nv_bfloat16* as = As + (size_t)cur * 128 * GPAD;
        __nv_bfloat16* bs = Bs + (size_t)cur * 128 * GPAD;
        #pragma unroll
        for (int kk = 0; kk < 2; kk++) {
            int kb = kk * 16;
            uint32_t afr[4][4], bfr[4][2];
            #pragma unroll
            for (int mt = 0; mt < 4; mt++) {
                int row = wm + mt * 16 + (lane & 15);
                int col = kb + (lane >> 4) * 8;
                ldsm_x4(afr[mt][0], afr[mt][1], afr[mt][2], afr[mt][3],
                        sptr(as + row * GPAD + col));
            }
            #pragma unroll
            for (int p = 0; p < 2; p++) {
                int row = wn + p * 16 + (lane & 7) + ((lane >> 4) & 1) * 8;
                int col = kb + ((lane >> 3) & 1) * 8;
                ldsm_x4(bfr[2*p][0], bfr[2*p][1], bfr[2*p+1][0], bfr[2*p+1][1],
                        sptr(bs + row * GPAD + col));
            }
            #pragma unroll
            for (int mt = 0; mt < 4; mt++)
                #pragma unroll
                for (int nt = 0; nt < 4; nt++)
                    mma_bf16(acc[mt][nt], afr[mt], bfr[nt]);
        }
    }
    #pragma unroll
    for (int mt = 0; mt < 4; mt++) {
        int r = m0 + wm + mt * 16 + (lane >> 2);
        #pragma unroll
        for (int nt = 0; nt < 4; nt++) {
            int col = n0 + wn + nt * 8 + (lane & 3) * 2;
            if (col < N) {
                *(float2*)(C + (size_t)r * N + col)       = make_float2(acc[mt][nt][0], acc[mt][nt][1]);
                *(float2*)(C + (size_t)(r + 8) * N + col) = make_float2(acc[mt][nt][2], acc[mt][nt][3]);
            }
        }
    }
}

// ---------------- big GEMM: 512 threads, 128x256 tile, K=512 ----------------
// MODE 1: merged attention scores (u = UGH partials, 4 slabs + attn_b)
// MODE 2: Ct = bf16(tanh(acc + bias))
template<int MODE>
__global__ __launch_bounds__(512) void big_gemm_k(
    const __nv_bfloat16* __restrict__ A, const __nv_bfloat16* __restrict__ Bw,
    const float* __restrict__ bias, __nv_bfloat16* __restrict__ Ct,
    float* __restrict__ spart, const float* __restrict__ up,
    const float* __restrict__ ab, const float* __restrict__ v, int N)
{
    constexpr int K = 512;
    extern __shared__ __align__(16) __nv_bfloat16 dsm[];
    __nv_bfloat16* As = dsm;                                   // [STG][128*GPAD]
    __nv_bfloat16* Bs = dsm + (size_t)STG * 128 * GPAD;        // [STG][256*GPAD]
    __shared__ float part[128][8];
    int tid = threadIdx.x;
    int warp = tid >> 5, lane = tid & 31;
    int m0 = blockIdx.y * 128, n0 = blockIdx.x * 256;
    int wm = (warp >> 3) * 64, wn = (warp & 7) * 32;

    float acc[4][4][4];
    #pragma unroll
    for (int i = 0; i < 4; i++)
        #pragma unroll
        for (int j = 0; j < 4; j++)
            #pragma unroll
            for (int q = 0; q < 4; q++) acc[i][j][q] = 0.f;

    int ar = tid >> 2, ac = (tid & 3) * 8;
    auto load_stage = [&](int st, int k0) {
        __nv_bfloat16* as = As + (size_t)st * 128 * GPAD;
        __nv_bfloat16* bs = Bs + (size_t)st * 256 * GPAD;
        cp16(sptr(as + ar * GPAD + ac), A + (size_t)(m0 + ar) * K + k0 + ac, true);
        #pragma unroll
        for (int s = 0; s < 2; s++) {
            int j = tid + s * 512;
            int br = j >> 2, bc = (j & 3) * 8;
            cp16(sptr(bs + br * GPAD + bc), Bw + (size_t)(n0 + br) * K + k0 + bc, true);
        }
        cp_commit();
    };

    constexpr int nk = K / 32;
    load_stage(0, 0);
    load_stage(1, 32);
    for (int it = 0; it < nk; it++) {
        if (it == nk - 1) cp_wait<0>(); else cp_wait<1>();
        __syncthreads();
        if (it + 2 < nk) load_stage((it + 2) % STG, (it + 2) * 32);
        int cur = it % STG;
        __nv_bfloat16* as = As + (size_t)cur * 128 * GPAD;
        __nv_bfloat16* bs = Bs + (size_t)cur * 256 * GPAD;
        #pragma unroll
        for (int kk = 0; kk < 2; kk++) {
            int kb = kk * 16;
            uint32_t afr[4][4], bfr[4][2];
            #pragma unroll
            for (int mt = 0; mt < 4; mt++) {
                int row = wm + mt * 16 + (lane & 15);
                int col = kb + (lane >> 4) * 8;
                ldsm_x4(afr[mt][0], afr[mt][1], afr[mt][2], afr[mt][3],
                        sptr(as + row * GPAD + col));
            }
            #pragma unroll
            for (int p = 0; p < 2; p++) {
                int row = wn + p * 16 + (lane & 7) + ((lane >> 4) & 1) * 8;
                int col = kb + ((lane >> 3) & 1) * 8;
                ldsm_x4(bfr[2*p][0], bfr[2*p][1], bfr[2*p+1][0], bfr[2*p+1][1],
                        sptr(bs + row * GPAD + col));
            }
            #pragma unroll
            for (int mt = 0; mt < 4; mt++)
                #pragma unroll
                for (int nt = 0; nt < 4; nt++)
                    mma_bf16(acc[mt][nt], afr[mt], bfr[nt]);
        }
    }

    if (MODE == 2) {
        #pragma unroll
        for (int mt = 0; mt < 4; mt++) {
            int r = m0 + wm + mt * 16 + (lane >> 2);
            #pragma unroll
            for (int nt = 0; nt < 4; nt++) {
                int col = n0 + wn + nt * 8 + (lane & 3) * 2;
                float b0 = bias[col], b1 = bias[col + 1];
                *(__nv_bfloat162*)(Ct + (size_t)r * N + col) =
                    __floats2bfloat162_rn(tanhf(acc[mt][nt][0] + b0), tanhf(acc[mt][nt][1] + b1));
                *(__nv_bfloat162*)(Ct + (size_t)(r + 8) * N + col) =
                    __floats2bfloat162_rn(tanhf(acc[mt][nt][2] + b0), tanhf(acc[mt][nt][3] + b1));
            }
        }
    } else {  // MODE 1
        #pragma unroll
        for (int mt = 0; mt < 4; mt++) {
            int r0 = wm + mt * 16 + (lane >> 2);
            int r1 = r0 + 8;
            const float* u0 = up + (size_t)bat_of(m0 + r0) * 2048;
            const float* u1 = up + (size_t)bat_of(m0 + r1) * 2048;
            float ls0 = 0.f, ls1 = 0.f;
            #pragma unroll
            for (int nt = 0; nt < 4; nt++) {
                int col = n0 + wn + nt * 8 + (lane & 3) * 2;
                #pragma unroll
                for (int q = 0; q < 2; q++) {
                    int c = col + q;
                    float uv0 = u0[c] + u0[USLAB + c] + u0[2*USLAB + c] + u0[3*USLAB + c] + ab[c];
                    float uv1 = u1[c] + u1[USLAB + c] + u1[2*USLAB + c] + u1[3*USLAB + c] + ab[c];
                    float vv = v[c];
                    ls0 += vv * tanhf(acc[mt][nt][q]     + uv0);
                    ls1 += vv * tanhf(acc[mt][nt][2 + q] + uv1);
                }
            }
            #pragma unroll
            for (int s = 1; s < 4; s <<= 1) {
                ls0 += __shfl_xor_sync(0xffffffffu, ls0, s);
                ls1 += __shfl_xor_sync(0xffffffffu, ls1, s);
            }
            if ((lane & 3) == 0) {
                part[r0][warp & 7] = ls0;
                part[r1][warp & 7] = ls1;
            }
        }
        __syncthreads();
        if (tid < 128) {
            float tot = 0.f;
            #pragma unroll
            for (int w = 0; w < 8; w++) tot += part[tid][w];
            spart[(size_t)(m0 + tid) * 2 + blockIdx.x] = tot;
        }
    }
}

// ---------------- merged softmax + ctx for all 3 segments ----------------
__global__ void softmax_ctx_all_k(const float* __restrict__ sp,
                                  const int* __restrict__ ids_u, const int* __restrict__ ids_b,
                                  const int* __restrict__ ids_p,
                                  const __nv_bfloat16* __restrict__ bf, float* __restrict__ x) {
    int b = blockIdx.x, chunk = blockIdx.y, seg = blockIdx.z, tid = threadIdx.x;
    int T; const int* ids; const __nv_bfloat16* enc; int tokbase;
    if (seg == 0)      { T = TU;  ids = ids_u; enc = bf + BOFF_EU; tokbase = 0; }
    else if (seg == 1) { T = TBt; ids = ids_b; enc = bf + BOFF_EB; tokbase = Bn*TU; }
    else               { T = TPt; ids = ids_p; enc = bf + BOFF_EP; tokbase = Bn*TU + Bn*TBt; }
    __shared__ float sw[256];
    __shared__ float red[256];
    float sv = -3.0e38f;
    if (tid < T) {
        const float* s2 = sp + (size_t)(tokbase + b * T + tid) * 2;
        sv = s2[0] + s2[1];
        if (ids[(size_t)b * T + tid] == 0) sv = NEGV;
    }
    red[tid] = sv; __syncthreads();
    for (int s = 128; s; s >>= 1) { if (tid < s) red[tid] = fmaxf(red[tid], red[tid + s]); __syncthreads(); }
    float m = red[0]; __syncthreads();
    float e = (tid < T) ? expf(sv - m) : 0.f;
    red[tid] = e; __syncthreads();
    for (int s = 128; s; s >>= 1) { if (tid < s) red[tid] += red[tid + s]; __syncthreads(); }
    float Z = red[0]; __syncthreads();
    sw[tid] = e / Z; __syncthreads();
    int h = chunk * 256 + tid;
    float acc = 0.f;
    const __nv_bfloat16* epp = enc + (size_t)b * T * Hd + h;
    #pragma unroll 4
    for (int t = 0; t < T; t++) acc += sw[t] * __bfloat162float(epp[(size_t)t * Hd]);
    x[(size_t)b * XD + Ed + seg * Hd + h] = acc;
}

// ---------------- x: emb + db slots ----------------
__global__ void fill_x_k(const int* __restrict__ w, const float* __restrict__ emb_table,
                         const float* __restrict__ db, float* __restrict__ x) {
    int b = blockIdx.x, tid = threadIdx.x;
    int wid = w[b];
    for (int i = tid; i < Ed; i += 256) x[(size_t)b * XD + i] = emb_table[(size_t)wid * Ed + i];
    for (int i = tid; i < PTRd; i += 256) x[(size_t)b * XD + Ed + 3 * Hd + i] = db[(size_t)b * PTRd + i];
}

// ---------------- GRU cell: reduce GI (5 slabs)+bih, GH (4 UGH slabs, cols 512+)+bhh ----------------
__global__ void gru_cell_k(const float* __restrict__ gip, const float* __restrict__ ughp,
                           const float* __restrict__ bih, const float* __restrict__ bhh,
                           const float* __restrict__ h0, float* __restrict__ hnew,
                           __nv_bfloat16* __restrict__ hnbf) {
    int i = blockIdx.x * 256 + threadIdx.x;
    if (i >= Bn * Hd) return;
    int b = i / Hd, j = i % Hd;
    float gi[3], gh[3];
    #pragma unroll
    for (int g = 0; g < 3; g++) {
        int col = g * Hd + j;
        float s = bih[col];
        #pragma unroll
        for (int z = 0; z < 5; z++) s += gip[(size_t)z * Bn * G3H + (size_t)b * G3H + col];
        gi[g] = s;
        float t = bhh[col];
        #pragma unroll
        for (int z = 0; z < 4; z++) t += ughp[(size_t)z * USLAB + (size_t)b * 2048 + 512 + col];
        gh[g] = t;
    }
    float r = sigmoidf_(gi[0] + gh[0]);
    float z = sigmoidf_(gi[1] + gh[1]);
    float n = tanhf(gi[2] + r * gh[2]);
    float hv = (1.f - z) * n + z * h0[i];
    hnew[i] = hv;
    hnbf[i] = __float2bfloat16(hv);
}

// ---------------- cp_raw: dot(hnew, tanhBCP) ----------------
__global__ void cpraw_k(const __nv_bfloat16* __restrict__ TB, const float* __restrict__ hnew,
                        const int* __restrict__ ids, float* __restrict__ cpr) {
    int tok = blockIdx.x * 8 + (threadIdx.x >> 5);
    int lane = threadIdx.x & 31;
    int b = tok / TBt;
    const __nv_bfloat162* e2 = (const __nv_bfloat162*)(TB + (size_t)tok * Hd);
    const float2* hn2 = (const float2*)(hnew + (size_t)b * Hd);
    float acc = 0.f;
    #pragma unroll 4
    for (int j = lane; j < Hd / 2; j += 32) {
        __nv_bfloat162 p = e2[j];
        float2 h2 = hn2[j];
        acc += h2.x * __bfloat162float(p.x) + h2.y * __bfloat162float(p.y);
    }
    #pragma unroll
    for (int s = 16; s; s >>= 1) acc += __shfl_down_sync(0xffffffffu, acc, s);
    if (lane == 0) cpr[tok] = (ids[tok] == 0) ? NEGV : acc;
}

// ---------------- final epilogue (reduces GEN partials) ----------------
__global__ void final_k(const float* __restrict__ genp, const float* __restrict__ genb,
                        const float* __restrict__ cpr, const int* __restrict__ nounk,
                        float* __restrict__ out) {
    int b = blockIdx.x, tid = threadIdx.x;
    __shared__ float Lg[Vd];
    __shared__ float Lc[Vd + TBt];
    __shared__ float addv[VOOVd - Vd];
    __shared__ float red[256];
    for (int n = tid; n < Vd; n += 256) {
        float s = genb[n];
        #pragma unroll
        for (int z = 0; z < 4; z++) s += genp[(size_t)z * Bn * Vd + (size_t)b * Vd + n];
        Lg[n] = s;
    }
    for (int n = tid; n < Vd + TBt; n += 256) Lc[n] = 0.f;
    for (int n = tid; n < VOOVd - Vd; n += 256) addv[n] = 0.f;
    __syncthreads();
    if (tid == 0) {
        for (int t = 0; t < TBt; t++) {
            int nk = nounk[(size_t)b * TBt + t];
            int col = (nk < Vd) ? nk : (Vd + t);
            Lc[col] += cpr[(size_t)b * TBt + t];
        }
    }
    __syncthreads();
    float lm = -3.0e38f;
    for (int n = tid; n < 2 * Vd + TBt; n += 256) {
        float v = (n < Vd) ? Lg[n] : Lc[n - Vd];
        lm = fmaxf(lm, v);
    }
    red[tid] = lm; __syncthreads();
    for (int s = 128; s; s >>= 1) { if (tid < s) red[tid] = fmaxf(red[tid], red[tid + s]); __syncthreads(); }
    float M = red[0]; __syncthreads();
    float ls = 0.f;
    for (int n = tid; n < 2 * Vd + TBt; n += 256) {
        float v = (n < Vd) ? Lg[n] : Lc[n - Vd];
        ls += expf(v - M);
    }
    red[tid] = ls; __syncthreads();
    for (int s = 128; s; s >>= 1) { if (tid < s) red[tid] += red[tid + s]; __syncthreads(); }
    float logZ = M + logf(red[0]); __syncthreads();
    if (tid == 0) {
        for (int t = 0; t < TBt; t++) {
            int nk = nounk[(size_t)b * TBt + t];
            if (nk >= Vd) addv[nk - Vd] += expf(Lc[Vd + t] - logZ);
        }
    }
    __syncthreads();
    for (int n = tid; n < VOOVd; n += 256) {
        float val;
        if (n < Vd) {
            float a = Lg[n] - logZ;
            float c = Lc[n] - logZ;
            float mm = fmaxf(a, c);
            val = mm + log1pf(expf(-fabsf(a - c)));
        } else {
            float v = addv[n - Vd];
            val = (v > 0.f) ? logf(fmaxf(v, 1e-38f)) : NEGV;
        }
        out[(size_t)b * VOOVd + n] = val;
    }
}

// ---------------- host ----------------
static inline int cdiv(int a, int b) { return (a + b - 1) / b; }

extern "C" void kernel_launch(void* const* d_in, const int* in_sizes, int n_in,
                              void* d_out, int out_size) {
    const int*   dec_last_w = (const int*)  d_in[0];
    const float* h0         = (const float*)d_in[1];
    const float* usdx_h     = (const float*)d_in[2];
    const float* bspn_h     = (const float*)d_in[3];
    const float* pv_h       = (const float*)d_in[4];
    const float* db         = (const float*)d_in[5];
    const int*   usdx_ids   = (const int*)  d_in[6];
    const int*   bspn_ids   = (const int*)  d_in[7];
    const int*   pv_ids     = (const int*)  d_in[8];
    const int*   nounk      = (const int*)  d_in[9];
    // d_in[10] = bspn_onehot: unused
    const float* emb        = (const float*)d_in[11];
    const float* attn_W     = (const float*)d_in[12];
    const float* attn_b     = (const float*)d_in[13];
    const float* v_w        = (const float*)d_in[14];
    const float* Wc         = (const float*)d_in[15];
    const float* Wcb        = (const float*)d_in[16];
    const float* Wg         = (const float*)d_in[17];
    const float* Wgb        = (const float*)d_in[18];
    const float* Wih        = (const float*)d_in[19];
    const float* Whh        = (const float*)d_in[20];
    const float* bih        = (const float*)d_in[21];
    const float* bhh        = (const float*)d_in[22];
    float* out = (float*)d_out;

    float* S = nullptr;  cudaGetSymbolAddress((void**)&S, g_scratch);
    __nv_bfloat16* Bf = nullptr;  cudaGetSymbolAddress((void**)&Bf, g_bf);

    float* UGHP = S + OFF_UGHP;
    float* GIP  = S + OFF_GIP;
    float* GENP = S + OFF_GENP;
    float* SP   = S + OFF_SP;
    float* X    = S + OFF_X;
    float* HNEW = S + OFF_HNEW;
    float* CPR  = S + OFF_CPR;

    __nv_bfloat16* bEU  = Bf + BOFF_EU;
    __nv_bfloat16* bEB  = Bf + BOFF_EB;
    __nv_bfloat16* bW1c = Bf + BOFF_W1;
    __nv_bfloat16* bW2  = Bf + BOFF_W2;
    __nv_bfloat16* bWC  = Bf + BOFF_WC;
    __nv_bfloat16* bWG  = Bf + BOFF_WG;
    __nv_bfloat16* bWIH = Bf + BOFF_WIH;
    __nv_bfloat16* bH0  = Bf + BOFF_H0;
    __nv_bfloat16* bX   = Bf + BOFF_X;
    __nv_bfloat16* bHN  = Bf + BOFF_HN;
    __nv_bfloat16* bTB  = Bf + BOFF_TBCP;

    static bool attr_set = false;
    if (!attr_set) {
        cudaFuncSetAttribute(skinny_gemm_k, cudaFuncAttributeMaxDynamicSharedMemorySize, DSMEM_SK);
        cudaFuncSetAttribute(big_gemm_k<1>, cudaFuncAttributeMaxDynamicSharedMemorySize, DSMEM_BIG);
        cudaFuncSetAttribute(big_gemm_k<2>, cudaFuncAttributeMaxDynamicSharedMemorySize, DSMEM_BIG);
        attr_set = true;
    }

    // 0: enc converts
    conv_enc_k<<<28672, 256>>>(usdx_h, bspn_h, pv_h, Bf);
    // 1: weight converts
    conv_weights_k<<<cdiv(6369280, 256), 256>>>(attn_W, Wc, Wg, Wih, Whh, h0, Bf);
    // 2: UGH partials (h0 @ [W1;Whh]^T), splitK=4
    skinny_gemm_k<<<dim3(16, 1, 4), 256, DSMEM_SK>>>(bH0, 512, bW1c, 512, UGHP, Bn, 2048, 128);
    // 3 (profiled slot): merged attention score GEMM
    big_gemm_k<1><<<dim3(2, MATT/128), 512, DSMEM_BIG>>>(bEU, bW2, nullptr, nullptr, SP, UGHP, attn_b, v_w, 512);
    // 4: copy GEMM -> tanh -> bf16
    big_gemm_k<2><<<dim3(2, (Bn*TBt)/128), 512, DSMEM_BIG>>>(bEB, bWC, Wcb, bTB, nullptr, nullptr, nullptr, nullptr, 512);
    // 5: softmax + ctx (all 3 segments)
    softmax_ctx_all_k<<<dim3(Bn, 2, 3), 256>>>(SP, usdx_ids, bspn_ids, pv_ids, Bf, X);
    // 6: emb + db
    fill_x_k<<<Bn, 256>>>(dec_last_w, emb, db, X);
    // 7: X -> bf16
    f2bf_k<<<cdiv(Bn*XD/4, 256), 256>>>(X, bX, Bn*XD/4);
    // 8: GI partials (x @ Wih^T), splitK=5, Kc=416
    skinny_gemm_k<<<dim3(12, 1, 5), 256, DSMEM_SK>>>(bX, XD, bWIH, XD, GIP, Bn, G3H, 416);
    // 9: GRU cell (reduces GI + GH partials)
    gru_cell_k<<<cdiv(Bn*Hd, 256), 256>>>(GIP, UGHP, bih, bhh, h0, HNEW, bHN);
    // 10: GEN partials (hnew @ Wg^T), splitK=4
    skinny_gemm_k<<<dim3(cdiv(3000, 128), 1, 4), 256, DSMEM_SK>>>(bHN, 512, bWG, 512, GENP, Bn, Vd, 128);
    // 11: copy scores
    cpraw_k<<<(Bn*TBt)/8, 256>>>(bTB, HNEW, bspn_ids, CPR);
    // 12: final epilogue (reduces GEN partials)
    final_k<<<Bn, 256>>>(GENP, Wgb, CPR, nounk, out);
}

// round 7
// speedup vs baseline: 7.4293x; 1.0049x over previous
#include <cuda_runtime.h>
#include <cuda_bf16.h>
#include <math.h>
#include <stdint.h>

// ---------------- problem constants ----------------
#define Bn    128
#define TU    256
#define TBt   128
#define TPt   64
#define Hd    512
#define Ed    512
#define Vd    3000
#define VOOVd 3400
#define PTRd  32
#define XD    2080
#define G3H   1536
#define NEGV  (-1e20f)
#define MATT  (Bn*TU + Bn*TBt + Bn*TPt)   // 57344 merged attention rows
#define YATT  (MATT/128)                   // 448 attention y-blocks
#define YCPY  ((Bn*TBt)/128)               // 128 copy y-blocks
#define USLAB (Bn*2048)

// ---------------- fp32 scratch ----------------
constexpr size_t OFF_UGHP = 0;                               // 4 x (B x 2048)
constexpr size_t OFF_GIP  = OFF_UGHP + (size_t)4*Bn*2048;    // 5 x (B x 1536)
constexpr size_t OFF_GENP = OFF_GIP  + (size_t)5*Bn*G3H;     // 4 x (B x 3000)
constexpr size_t OFF_SP   = OFF_GENP + (size_t)4*Bn*Vd;      // MATT x 2 score partials
constexpr size_t OFF_X    = OFF_SP   + (size_t)MATT*2;       // B x 2080
constexpr size_t OFF_HNEW = OFF_X    + (size_t)Bn*XD;
constexpr size_t OFF_CPR  = OFF_HNEW + (size_t)Bn*Hd;
constexpr size_t TOT_F32  = OFF_CPR  + (size_t)Bn*TBt;
__device__ float g_scratch[TOT_F32];

// ---------------- bf16 scratch ----------------
constexpr size_t BOFF_EU   = 0;
constexpr size_t BOFF_EB   = BOFF_EU  + (size_t)Bn*TU*Hd;
constexpr size_t BOFF_EP   = BOFF_EB  + (size_t)Bn*TBt*Hd;
constexpr size_t BOFF_W1   = BOFF_EP  + (size_t)Bn*TPt*Hd;   // 512x512
constexpr size_t BOFF_WHH  = BOFF_W1  + (size_t)512*512;     // 1536x512
constexpr size_t BOFF_W2   = BOFF_WHH + (size_t)1536*512;
constexpr size_t BOFF_WC   = BOFF_W2  + (size_t)512*512;
constexpr size_t BOFF_WG   = BOFF_WC  + (size_t)512*512;     // 3000x512
constexpr size_t BOFF_WIH  = BOFF_WG  + (size_t)3000*512;    // 1536x2080
constexpr size_t BOFF_H0   = BOFF_WIH + (size_t)1536*2080;   // 128x512
constexpr size_t BOFF_X    = BOFF_H0  + (size_t)Bn*Hd;       // 128x2080
constexpr size_t BOFF_HN   = BOFF_X   + (size_t)Bn*XD;       // 128x512
constexpr size_t BOFF_TBCP = BOFF_HN  + (size_t)Bn*Hd;       // 16384x512 tanh(copy)
constexpr size_t TOT_BF    = BOFF_TBCP+ (size_t)Bn*TBt*Hd;
__device__ __nv_bfloat16 g_bf[TOT_BF];

__device__ __forceinline__ float sigmoidf_(float x) { return 1.0f / (1.0f + expf(-x)); }

// ---------------- converts ----------------
__global__ void conv_enc_k(const float* __restrict__ eu, const float* __restrict__ eb,
                           const float* __restrict__ ep, __nv_bfloat16* __restrict__ bf) {
    int i = blockIdx.x * 256 + threadIdx.x;
    float4 v; __nv_bfloat16* d;
    if (i < 4194304)      { v = ((const float4*)eu)[i]; d = bf + BOFF_EU + (size_t)i * 4; }
    else if (i < 6291456) { int j = i - 4194304; v = ((const float4*)eb)[j]; d = bf + BOFF_EB + (size_t)j * 4; }
    else if (i < 7340032) { int j = i - 6291456; v = ((const float4*)ep)[j]; d = bf + BOFF_EP + (size_t)j * 4; }
    else return;
    ((__nv_bfloat162*)d)[0] = __floats2bfloat162_rn(v.x, v.y);
    ((__nv_bfloat162*)d)[1] = __floats2bfloat162_rn(v.z, v.w);
}

__global__ void conv_weights_k(const float* __restrict__ aw, const float* __restrict__ wc,
                               const float* __restrict__ wg, const float* __restrict__ wih,
                               const float* __restrict__ whh, const float* __restrict__ h0,
                               __nv_bfloat16* __restrict__ bf) {
    int i = blockIdx.x * 256 + threadIdx.x;
    if (i < 262144)       { int r = i >> 9, c = i & 511; bf[BOFF_W1 + i] = __float2bfloat16(aw[(size_t)r * 1024 + c]); }
    else if (i < 524288)  { int j = i - 262144; int r = j >> 9, c = j & 511; bf[BOFF_W2 + j] = __float2bfloat16(aw[(size_t)r * 1024 + 512 + c]); }
    else if (i < 786432)  { int j = i - 524288;  bf[BOFF_WC  + j] = __float2bfloat16(wc[j]); }
    else if (i < 2322432) { int j = i - 786432;  bf[BOFF_WG  + j] = __float2bfloat16(wg[j]); }
    else if (i < 5517312) { int j = i - 2322432; bf[BOFF_WIH + j] = __float2bfloat16(wih[j]); }
    else if (i < 6303744) { int j = i - 5517312; bf[BOFF_WHH + j] = __float2bfloat16(whh[j]); }
    else if (i < 6369280) { int j = i - 6303744; bf[BOFF_H0  + j] = __float2bfloat16(h0[j]); }
}

__global__ void f2bf_k(const float* __restrict__ in, __nv_bfloat16* __restrict__ outp, int n4) {
    int i = blockIdx.x * 256 + threadIdx.x;
    if (i >= n4) return;
    float4 v = ((const float4*)in)[i];
    ((__nv_bfloat162*)outp)[2*i]   = __floats2bfloat162_rn(v.x, v.y);
    ((__nv_bfloat162*)outp)[2*i+1] = __floats2bfloat162_rn(v.z, v.w);
}

// ---------------- mma helpers ----------------
__device__ __forceinline__ uint32_t sptr(const void* p) {
    return (uint32_t)__cvta_generic_to_shared(p);
}
__device__ __forceinline__ void ldsm_x4(uint32_t& r0, uint32_t& r1, uint32_t& r2, uint32_t& r3, uint32_t a) {
    asm volatile("ldmatrix.sync.aligned.m8n8.x4.shared.b16 {%0,%1,%2,%3}, [%4];\n"
                 : "=r"(r0), "=r"(r1), "=r"(r2), "=r"(r3) : "r"(a));
}
__device__ __forceinline__ void mma_bf16(float* d, const uint32_t* a, const uint32_t* b) {
    asm volatile("mma.sync.aligned.m16n8k16.row.col.f32.bf16.bf16.f32 "
                 "{%0,%1,%2,%3},{%4,%5,%6,%7},{%8,%9},{%0,%1,%2,%3};\n"
                 : "+f"(d[0]), "+f"(d[1]), "+f"(d[2]), "+f"(d[3])
                 : "r"(a[0]), "r"(a[1]), "r"(a[2]), "r"(a[3]), "r"(b[0]), "r"(b[1]));
}
__device__ __forceinline__ void cp16(uint32_t dst, const void* src, bool pred) {
    int sz = pred ? 16 : 0;
    asm volatile("cp.async.cg.shared.global [%0], [%1], 16, %2;\n"
                 :: "r"(dst), "l"(src), "r"(sz));
}
__device__ __forceinline__ void cp_commit() { asm volatile("cp.async.commit_group;\n"); }
template<int Nw> __device__ __forceinline__ void cp_wait() {
    asm volatile("cp.async.wait_group %0;\n" :: "n"(Nw));
}

#define GPAD 40
#define SKSTG 3
#define BSTG  4
constexpr int DSMEM_SK  = SKSTG * 2 * 128 * GPAD * 2;          // 61440
constexpr int DSMEM_BIG = BSTG * (128 + 256) * GPAD * 2;       // 122880

__device__ __forceinline__ int bat_of(int r) {
    return (r < Bn*TU) ? (r >> 8)
         : (r < Bn*TU + Bn*TBt) ? ((r - Bn*TU) >> 7)
         : ((r - Bn*TU - Bn*TBt) >> 6);
}

// ---------------- skinny split-K GEMM (M=128 tiles) ----------------
__global__ __launch_bounds__(256) void skinny_gemm_k(
    const __nv_bfloat16* __restrict__ A, int lda,
    const __nv_bfloat16* __restrict__ Bw, int ldb,
    float* __restrict__ Cp, int M, int N, int Kc)
{
    extern __shared__ __align__(16) __nv_bfloat16 dsm[];
    __nv_bfloat16* As = dsm;
    __nv_bfloat16* Bs = dsm + (size_t)SKSTG * 128 * GPAD;
    int tid = threadIdx.x;
    int warp = tid >> 5, lane = tid & 31;
    int m0 = blockIdx.y * 128, n0 = blockIdx.x * 128;
    int koff = blockIdx.z * Kc;
    float* C = Cp + (size_t)blockIdx.z * M * N;
    int wm = (warp >> 2) * 64, wn = (warp & 3) * 32;

    float acc[4][4][4];
    #pragma unroll
    for (int i = 0; i < 4; i++)
        #pragma unroll
        for (int j = 0; j < 4; j++)
            #pragma unroll
            for (int q = 0; q < 4; q++) acc[i][j][q] = 0.f;

    int lr = tid >> 1;
    int lc0 = (tid & 1) * 16;
    auto load_stage = [&](int st, int k0) {
        __nv_bfloat16* as = As + (size_t)st * 128 * GPAD;
        __nv_bfloat16* bs = Bs + (size_t)st * 128 * GPAD;
        #pragma unroll
        for (int s = 0; s < 2; s++) {
            int c = lc0 + s * 8;
            cp16(sptr(as + lr * GPAD + c), A + (size_t)(m0 + lr) * lda + koff + k0 + c, true);
            int gn = n0 + lr;
            bool pred = gn < N;
            cp16(sptr(bs + lr * GPAD + c),
                 Bw + (size_t)(pred ? gn : (N - 1)) * ldb + koff + k0 + c, pred);
        }
        cp_commit();
    };

    int nk = Kc >> 5;
    load_stage(0, 0);
    load_stage(1, 32);
    for (int it = 0; it < nk; it++) {
        if (it == nk - 1) cp_wait<0>(); else cp_wait<1>();
        __syncthreads();
        if (it + 2 < nk) load_stage((it + 2) % SKSTG, (it + 2) * 32);
        int cur = it % SKSTG;
        __nv_bfloat16* as = As + (size_t)cur * 128 * GPAD;
        __nv_bfloat16* bs = Bs + (size_t)cur * 128 * GPAD;
        #pragma unroll
        for (int kk = 0; kk < 2; kk++) {
            int kb = kk * 16;
            uint32_t afr[4][4], bfr[4][2];
            #pragma unroll
            for (int mt = 0; mt < 4; mt++) {
                int row = wm + mt * 16 + (lane & 15);
                int col = kb + (lane >> 4) * 8;
                ldsm_x4(afr[mt][0], afr[mt][1], afr[mt][2], afr[mt][3],
                        sptr(as + row * GPAD + col));
            }
            #pragma unroll
            for (int p = 0; p < 2; p++) {
                int row = wn + p * 16 + (lane & 7) + ((lane >> 4) & 1) * 8;
                int col = kb + ((lane >> 3) & 1) * 8;
                ldsm_x4(bfr[2*p][0], bfr[2*p][1], bfr[2*p+1][0], bfr[2*p+1][1],
                        sptr(bs + row * GPAD + col));
            }
            #pragma unroll
            for (int mt = 0; mt < 4; mt++)
                #pragma unroll
                for (int nt = 0; nt < 4; nt++)
                    mma_bf16(acc[mt][nt], afr[mt], bfr[nt]);
        }
    }
    #pragma unroll
    for (int mt = 0; mt < 4; mt++) {
        int r = m0 + wm + mt * 16 + (lane >> 2);
        #pragma unroll
        for (int nt = 0; nt < 4; nt++) {
            int col = n0 + wn + nt * 8 + (lane & 3) * 2;
            if (col < N) {
                *(float2*)(C + (size_t)r * N + col)       = make_float2(acc[mt][nt][0], acc[mt][nt][1]);
                *(float2*)(C + (size_t)(r + 8) * N + col) = make_float2(acc[mt][nt][2], acc[mt][nt][3]);
            }
        }
    }
}

// ---------------- fused big GEMM: attention-score blocks + copy-tanh blocks ----------------
// grid: (2, YATT+YCPY). by < YATT: A=EU..EP rows vs W2, score epilogue.
//       else: A=EB rows vs WC, tanh epilogue -> bTB.
// 512 threads, 128x256 tile, 4x4 warp grid (32x64 per warp), K=512, 4-stage pipe.
__global__ __launch_bounds__(512) void fused_gemm_k(
    const __nv_bfloat16* __restrict__ bf, const float* __restrict__ wcb,
    __nv_bfloat16* __restrict__ bTB, float* __restrict__ spart,
    const float* __restrict__ up, const float* __restrict__ ab,
    const float* __restrict__ v)
{
    constexpr int K = 512;
    constexpr int N = 512;
    extern __shared__ __align__(16) __nv_bfloat16 dsm[];
    __nv_bfloat16* As = dsm;                                   // [BSTG][128*GPAD]
    __nv_bfloat16* Bs = dsm + (size_t)BSTG * 128 * GPAD;       // [BSTG][256*GPAD]
    __shared__ float part[128][4];
    int tid = threadIdx.x;
    int warp = tid >> 5, lane = tid & 31;
    int by = blockIdx.y;
    bool isAtt = by < YATT;
    const __nv_bfloat16* A  = isAtt ? (bf + BOFF_EU) : (bf + BOFF_EB);
    const __nv_bfloat16* Bw = isAtt ? (bf + BOFF_W2) : (bf + BOFF_WC);
    int m0 = (isAtt ? by : (by - YATT)) * 128;
    int n0 = blockIdx.x * 256;
    int wm = (warp >> 2) * 32, wn = (warp & 3) * 64;

    float acc[2][8][4];
    #pragma unroll
    for (int i = 0; i < 2; i++)
        #pragma unroll
        for (int j = 0; j < 8; j++)
            #pragma unroll
            for (int q = 0; q < 4; q++) acc[i][j][q] = 0.f;

    int ar = tid >> 2, ac = (tid & 3) * 8;
    auto load_stage = [&](int st, int k0) {
        __nv_bfloat16* as = As + (size_t)st * 128 * GPAD;
        __nv_bfloat16* bs = Bs + (size_t)st * 256 * GPAD;
        cp16(sptr(as + ar * GPAD + ac), A + (size_t)(m0 + ar) * K + k0 + ac, true);
        #pragma unroll
        for (int s = 0; s < 2; s++) {
            int j = tid + s * 512;
            int br = j >> 2, bc = (j & 3) * 8;
            cp16(sptr(bs + br * GPAD + bc), Bw + (size_t)(n0 + br) * K + k0 + bc, true);
        }
        cp_commit();
    };

    constexpr int nk = K / 32;   // 16
    load_stage(0, 0);
    load_stage(1, 32);
    load_stage(2, 64);
    for (int it = 0; it < nk; it++) {
        if (it + 3 < nk) { load_stage((it + 3) & 3, (it + 3) * 32); cp_wait<3>(); }
        else {
            int rem = nk - 1 - it;
            if (rem == 2) cp_wait<2>();
            else if (rem == 1) cp_wait<1>();
            else cp_wait<0>();
        }
        __syncthreads();
        int cur = it & 3;
        __nv_bfloat16* as = As + (size_t)cur * 128 * GPAD;
        __nv_bfloat16* bs = Bs + (size_t)cur * 256 * GPAD;
        #pragma unroll
        for (int kk = 0; kk < 2; kk++) {
            int kb = kk * 16;
            uint32_t afr[2][4], bfr[8][2];
            #pragma unroll
            for (int mt = 0; mt < 2; mt++) {
                int row = wm + mt * 16 + (lane & 15);
                int col = kb + (lane >> 4) * 8;
                ldsm_x4(afr[mt][0], afr[mt][1], afr[mt][2], afr[mt][3],
                        sptr(as + row * GPAD + col));
            }
            #pragma unroll
            for (int p = 0; p < 4; p++) {
                int row = wn + p * 16 + (lane & 7) + ((lane >> 4) & 1) * 8;
                int col = kb + ((lane >> 3) & 1) * 8;
                ldsm_x4(bfr[2*p][0], bfr[2*p][1], bfr[2*p+1][0], bfr[2*p+1][1],
                        sptr(bs + row * GPAD + col));
            }
            #pragma unroll
            for (int mt = 0; mt < 2; mt++)
                #pragma unroll
                for (int nt = 0; nt < 8; nt++)
                    mma_bf16(acc[mt][nt], afr[mt], bfr[nt]);
        }
        __syncthreads();
    }

    if (!isAtt) {
        // tanh epilogue -> bf16 bTB
        #pragma unroll
        for (int mt = 0; mt < 2; mt++) {
            int r = m0 + wm + mt * 16 + (lane >> 2);
            #pragma unroll
            for (int nt = 0; nt < 8; nt++) {
                int col = n0 + wn + nt * 8 + (lane & 3) * 2;
                float b0 = wcb[col], b1 = wcb[col + 1];
                *(__nv_bfloat162*)(bTB + (size_t)r * N + col) =
                    __floats2bfloat162_rn(tanhf(acc[mt][nt][0] + b0), tanhf(acc[mt][nt][1] + b1));
                *(__nv_bfloat162*)(bTB + (size_t)(r + 8) * N + col) =
                    __floats2bfloat162_rn(tanhf(acc[mt][nt][2] + b0), tanhf(acc[mt][nt][3] + b1));
            }
        }
    } else {
        // score epilogue
        #pragma unroll
        for (int mt = 0; mt < 2; mt++) {
            int r0 = wm + mt * 16 + (lane >> 2);
            int r1 = r0 + 8;
            const float* u0 = up + (size_t)bat_of(m0 + r0) * 2048;
            const float* u1 = up + (size_t)bat_of(m0 + r1) * 2048;
            float ls0 = 0.f, ls1 = 0.f;
            #pragma unroll
            for (int nt = 0; nt < 8; nt++) {
                int col = n0 + wn + nt * 8 + (lane & 3) * 2;
                #pragma unroll
                for (int q = 0; q < 2; q++) {
                    int c = col + q;
                    float uv0 = u0[c] + u0[USLAB + c] + u0[2*USLAB + c] + u0[3*USLAB + c] + ab[c];
                    float uv1 = u1[c] + u1[USLAB + c] + u1[2*USLAB + c] + u1[3*USLAB + c] + ab[c];
                    float vv = v[c];
                    ls0 += vv * tanhf(acc[mt][nt][q]     + uv0);
                    ls1 += vv * tanhf(acc[mt][nt][2 + q] + uv1);
                }
            }
            #pragma unroll
            for (int s = 1; s < 4; s <<= 1) {
                ls0 += __shfl_xor_sync(0xffffffffu, ls0, s);
                ls1 += __shfl_xor_sync(0xffffffffu, ls1, s);
            }
            if ((lane & 3) == 0) {
                part[r0][warp & 3] = ls0;
                part[r1][warp & 3] = ls1;
            }
        }
        __syncthreads();
        if (tid < 128) {
            float tot = part[tid][0] + part[tid][1] + part[tid][2] + part[tid][3];
            spart[(size_t)(m0 + tid) * 2 + blockIdx.x] = tot;
        }
    }
}

// ---------------- merged softmax + ctx for all 3 segments ----------------
__global__ void softmax_ctx_all_k(const float* __restrict__ sp,
                                  const int* __restrict__ ids_u, const int* __restrict__ ids_b,
                                  const int* __restrict__ ids_p,
                                  const __nv_bfloat16* __restrict__ bf, float* __restrict__ x) {
    int b = blockIdx.x, chunk = blockIdx.y, seg = blockIdx.z, tid = threadIdx.x;
    int T; const int* ids; const __nv_bfloat16* enc; int tokbase;
    if (seg == 0)      { T = TU;  ids = ids_u; enc = bf + BOFF_EU; tokbase = 0; }
    else if (seg == 1) { T = TBt; ids = ids_b; enc = bf + BOFF_EB; tokbase = Bn*TU; }
    else               { T = TPt; ids = ids_p; enc = bf + BOFF_EP; tokbase = Bn*TU + Bn*TBt; }
    __shared__ float sw[256];
    __shared__ float red[256];
    float sv = -3.0e38f;
    if (tid < T) {
        const float* s2 = sp + (size_t)(tokbase + b * T + tid) * 2;
        sv = s2[0] + s2[1];
        if (ids[(size_t)b * T + tid] == 0) sv = NEGV;
    }
    red[tid] = sv; __syncthreads();
    for (int s = 128; s; s >>= 1) { if (tid < s) red[tid] = fmaxf(red[tid], red[tid + s]); __syncthreads(); }
    float m = red[0]; __syncthreads();
    float e = (tid < T) ? expf(sv - m) : 0.f;
    red[tid] = e; __syncthreads();
    for (int s = 128; s; s >>= 1) { if (tid < s) red[tid] += red[tid + s]; __syncthreads(); }
    float Z = red[0]; __syncthreads();
    sw[tid] = e / Z; __syncthreads();
    int h = chunk * 256 + tid;
    float acc = 0.f;
    const __nv_bfloat16* epp = enc + (size_t)b * T * Hd + h;
    #pragma unroll 4
    for (int t = 0; t < T; t++) acc += sw[t] * __bfloat162float(epp[(size_t)t * Hd]);
    x[(size_t)b * XD + Ed + seg * Hd + h] = acc;
}

// ---------------- x: emb + db slots ----------------
__global__ void fill_x_k(const int* __restrict__ w, const float* __restrict__ emb_table,
                         const float* __restrict__ db, float* __restrict__ x) {
    int b = blockIdx.x, tid = threadIdx.x;
    int wid = w[b];
    for (int i = tid; i < Ed; i += 256) x[(size_t)b * XD + i] = emb_table[(size_t)wid * Ed + i];
    for (int i = tid; i < PTRd; i += 256) x[(size_t)b * XD + Ed + 3 * Hd + i] = db[(size_t)b * PTRd + i];
}

// ---------------- GRU cell ----------------
__global__ void gru_cell_k(const float* __restrict__ gip, const float* __restrict__ ughp,
                           const float* __restrict__ bih, const float* __restrict__ bhh,
                           const float* __restrict__ h0, float* __restrict__ hnew,
                           __nv_bfloat16* __restrict__ hnbf) {
    int i = blockIdx.x * 256 + threadIdx.x;
    if (i >= Bn * Hd) return;
    int b = i / Hd, j = i % Hd;
    float gi[3], gh[3];
    #pragma unroll
    for (int g = 0; g < 3; g++) {
        int col = g * Hd + j;
        float s = bih[col];
        #pragma unroll
        for (int z = 0; z < 5; z++) s += gip[(size_t)z * Bn * G3H + (size_t)b * G3H + col];
        gi[g] = s;
        float t = bhh[col];
        #pragma unroll
        for (int z = 0; z < 4; z++) t += ughp[(size_t)z * USLAB + (size_t)b * 2048 + 512 + col];
        gh[g] = t;
    }
    float r = sigmoidf_(gi[0] + gh[0]);
    float z = sigmoidf_(gi[1] + gh[1]);
    float n = tanhf(gi[2] + r * gh[2]);
    float hv = (1.f - z) * n + z * h0[i];
    hnew[i] = hv;
    hnbf[i] = __float2bfloat16(hv);
}

// ---------------- cp_raw ----------------
__global__ void cpraw_k(const __nv_bfloat16* __restrict__ TB, const float* __restrict__ hnew,
                        const int* __restrict__ ids, float* __restrict__ cpr) {
    int tok = blockIdx.x * 8 + (threadIdx.x >> 5);
    int lane = threadIdx.x & 31;
    int b = tok / TBt;
    const __nv_bfloat162* e2 = (const __nv_bfloat162*)(TB + (size_t)tok * Hd);
    const float2* hn2 = (const float2*)(hnew + (size_t)b * Hd);
    float acc = 0.f;
    #pragma unroll 4
    for (int j = lane; j < Hd / 2; j += 32) {
        __nv_bfloat162 p = e2[j];
        float2 h2 = hn2[j];
        acc += h2.x * __bfloat162float(p.x) + h2.y * __bfloat162float(p.y);
    }
    #pragma unroll
    for (int s = 16; s; s >>= 1) acc += __shfl_down_sync(0xffffffffu, acc, s);
    if (lane == 0) cpr[tok] = (ids[tok] == 0) ? NEGV : acc;
}

// ---------------- final epilogue ----------------
__global__ void final_k(const float* __restrict__ genp, const float* __restrict__ genb,
                        const float* __restrict__ cpr, const int* __restrict__ nounk,
                        float* __restrict__ out) {
    int b = blockIdx.x, tid = threadIdx.x;
    __shared__ float Lg[Vd];
    __shared__ float Lc[Vd + TBt];
    __shared__ float addv[VOOVd - Vd];
    __shared__ float red[256];
    for (int n = tid; n < Vd; n += 256) {
        float s = genb[n];
        #pragma unroll
        for (int z = 0; z < 4; z++) s += genp[(size_t)z * Bn * Vd + (size_t)b * Vd + n];
        Lg[n] = s;
    }
    for (int n = tid; n < Vd + TBt; n += 256) Lc[n] = 0.f;
    for (int n = tid; n < VOOVd - Vd; n += 256) addv[n] = 0.f;
    __syncthreads();
    if (tid == 0) {
        for (int t = 0; t < TBt; t++) {
            int nk = nounk[(size_t)b * TBt + t];
            int col = (nk < Vd) ? nk : (Vd + t);
            Lc[col] += cpr[(size_t)b * TBt + t];
        }
    }
    __syncthreads();
    float lm = -3.0e38f;
    for (int n = tid; n < 2 * Vd + TBt; n += 256) {
        float v = (n < Vd) ? Lg[n] : Lc[n - Vd];
        lm = fmaxf(lm, v);
    }
    red[tid] = lm; __syncthreads();
    for (int s = 128; s; s >>= 1) { if (tid < s) red[tid] = fmaxf(red[tid], red[tid + s]); __syncthreads(); }
    float M = red[0]; __syncthreads();
    float ls = 0.f;
    for (int n = tid; n < 2 * Vd + TBt; n += 256) {
        float v = (n < Vd) ? Lg[n] : Lc[n - Vd];
        ls += expf(v - M);
    }
    red[tid] = ls; __syncthreads();
    for (int s = 128; s; s >>= 1) { if (tid < s) red[tid] += red[tid + s]; __syncthreads(); }
    float logZ = M + logf(red[0]); __syncthreads();
    if (tid == 0) {
        for (int t = 0; t < TBt; t++) {
            int nk = nounk[(size_t)b * TBt + t];
            if (nk >= Vd) addv[nk - Vd] += expf(Lc[Vd + t] - logZ);
        }
    }
    __syncthreads();
    for (int n = tid; n < VOOVd; n += 256) {
        float val;
        if (n < Vd) {
            float a = Lg[n] - logZ;
            float c = Lc[n] - logZ;
            float mm = fmaxf(a, c);
            val = mm + log1pf(expf(-fabsf(a - c)));
        } else {
            float v = addv[n - Vd];
            val = (v > 0.f) ? logf(fmaxf(v, 1e-38f)) : NEGV;
        }
        out[(size_t)b * VOOVd + n] = val;
    }
}

// ---------------- host ----------------
static inline int cdiv(int a, int b) { return (a + b - 1) / b; }

extern "C" void kernel_launch(void* const* d_in, const int* in_sizes, int n_in,
                              void* d_out, int out_size) {
    const int*   dec_last_w = (const int*)  d_in[0];
    const float* h0         = (const float*)d_in[1];
    const float* usdx_h     = (const float*)d_in[2];
    const float* bspn_h     = (const float*)d_in[3];
    const float* pv_h       = (const float*)d_in[4];
    const float* db         = (const float*)d_in[5];
    const int*   usdx_ids   = (const int*)  d_in[6];
    const int*   bspn_ids   = (const int*)  d_in[7];
    const int*   pv_ids     = (const int*)  d_in[8];
    const int*   nounk      = (const int*)  d_in[9];
    // d_in[10] = bspn_onehot: unused
    const float* emb        = (const float*)d_in[11];
    const float* attn_W     = (const float*)d_in[12];
    const float* attn_b     = (const float*)d_in[13];
    const float* v_w        = (const float*)d_in[14];
    const float* Wc         = (const float*)d_in[15];
    const float* Wcb        = (const float*)d_in[16];
    const float* Wg         = (const float*)d_in[17];
    const float* Wgb        = (const float*)d_in[18];
    const float* Wih        = (const float*)d_in[19];
    const float* Whh        = (const float*)d_in[20];
    const float* bih        = (const float*)d_in[21];
    const float* bhh        = (const float*)d_in[22];
    float* out = (float*)d_out;

    float* S = nullptr;  cudaGetSymbolAddress((void**)&S, g_scratch);
    __nv_bfloat16* Bf = nullptr;  cudaGetSymbolAddress((void**)&Bf, g_bf);

    float* UGHP = S + OFF_UGHP;
    float* GIP  = S + OFF_GIP;
    float* GENP = S + OFF_GENP;
    float* SP   = S + OFF_SP;
    float* X    = S + OFF_X;
    float* HNEW = S + OFF_HNEW;
    float* CPR  = S + OFF_CPR;

    __nv_bfloat16* bW1c = Bf + BOFF_W1;
    __nv_bfloat16* bWG  = Bf + BOFF_WG;
    __nv_bfloat16* bWIH = Bf + BOFF_WIH;
    __nv_bfloat16* bH0  = Bf + BOFF_H0;
    __nv_bfloat16* bX   = Bf + BOFF_X;
    __nv_bfloat16* bHN  = Bf + BOFF_HN;
    __nv_bfloat16* bTB  = Bf + BOFF_TBCP;

    static bool attr_set = false;
    if (!attr_set) {
        cudaFuncSetAttribute(skinny_gemm_k, cudaFuncAttributeMaxDynamicSharedMemorySize, DSMEM_SK);
        cudaFuncSetAttribute(fused_gemm_k, cudaFuncAttributeMaxDynamicSharedMemorySize, DSMEM_BIG);
        attr_set = true;
    }

    // 0: enc converts
    conv_enc_k<<<28672, 256>>>(usdx_h, bspn_h, pv_h, Bf);
    // 1: weight converts
    conv_weights_k<<<cdiv(6369280, 256), 256>>>(attn_W, Wc, Wg, Wih, Whh, h0, Bf);
    // 2: UGH partials, splitK=4
    skinny_gemm_k<<<dim3(16, 1, 4), 256, DSMEM_SK>>>(bH0, 512, bW1c, 512, UGHP, Bn, 2048, 128);
    // 3 (profiled slot): fused attention-score + copy-tanh GEMM
    fused_gemm_k<<<dim3(2, YATT + YCPY), 512, DSMEM_BIG>>>(Bf, Wcb, bTB, SP, UGHP, attn_b, v_w);
    // 4: softmax + ctx
    softmax_ctx_all_k<<<dim3(Bn, 2, 3), 256>>>(SP, usdx_ids, bspn_ids, pv_ids, Bf, X);
    // 5: emb + db
    fill_x_k<<<Bn, 256>>>(dec_last_w, emb, db, X);
    // 6: X -> bf16
    f2bf_k<<<cdiv(Bn*XD/4, 256), 256>>>(X, bX, Bn*XD/4);
    // 7: GI partials, splitK=5, Kc=416
    skinny_gemm_k<<<dim3(12, 1, 5), 256, DSMEM_SK>>>(bX, XD, bWIH, XD, GIP, Bn, G3H, 416);
    // 8: GRU cell
    gru_cell_k<<<cdiv(Bn*Hd, 256), 256>>>(GIP, UGHP, bih, bhh, h0, HNEW, bHN);
    // 9: GEN partials, splitK=4
    skinny_gemm_k<<<dim3(cdiv(3000, 128), 1, 4), 256, DSMEM_SK>>>(bHN, 512, bWG, 512, GENP, Bn, Vd, 128);
    // 10: copy scores
    cpraw_k<<<(Bn*TBt)/8, 256>>>(bTB, HNEW, bspn_ids, CPR);
    // 11: final epilogue
    final_k<<<Bn, 256>>>(GENP, Wgb, CPR, nounk, out);
}

// round 10
// speedup vs baseline: 8.0820x; 1.0879x over previous
#include <cuda_runtime.h>
#include <cuda_bf16.h>
#include <math.h>
#include <stdint.h>

// ---------------- problem constants ----------------
#define Bn    128
#define TU    256
#define TBt   128
#define TPt   64
#define Hd    512
#define Ed    512
#define Vd    3000
#define VOOVd 3400
#define PTRd  32
#define XD    2080
#define G3H   1536
#define NEGV  (-1e20f)
#define MATT  (Bn*TU + Bn*TBt + Bn*TPt)   // 57344 merged attention rows
#define YATT  (MATT/128)                   // 448 attention y-blocks
#define YCPY  ((Bn*TBt)/128)               // 128 copy y-blocks
#define USLAB (Bn*2048)

// ---------------- fp32 scratch ----------------
constexpr size_t OFF_UGHP = 0;                               // 4 x (B x 2048)
constexpr size_t OFF_GIP  = OFF_UGHP + (size_t)4*Bn*2048;    // 5 x (B x 1536)
constexpr size_t OFF_GENP = OFF_GIP  + (size_t)5*Bn*G3H;     // 4 x (B x 3000)
constexpr size_t OFF_SP   = OFF_GENP + (size_t)4*Bn*Vd;      // MATT x 2 score partials
constexpr size_t OFF_X    = OFF_SP   + (size_t)MATT*2;       // B x 2080
constexpr size_t OFF_HNEW = OFF_X    + (size_t)Bn*XD;
constexpr size_t OFF_CPR  = OFF_HNEW + (size_t)Bn*Hd;
constexpr size_t TOT_F32  = OFF_CPR  + (size_t)Bn*TBt;
__device__ float g_scratch[TOT_F32];

// ---------------- bf16 scratch (weights + small activations + tanh-copy) ----------------
constexpr size_t BOFF_W1   = 0;                              // 512x512
constexpr size_t BOFF_WHH  = BOFF_W1  + (size_t)512*512;     // 1536x512 (contiguous after W1)
constexpr size_t BOFF_W2   = BOFF_WHH + (size_t)1536*512;
constexpr size_t BOFF_WC   = BOFF_W2  + (size_t)512*512;
constexpr size_t BOFF_WG   = BOFF_WC  + (size_t)512*512;     // 3000x512
constexpr size_t BOFF_WIH  = BOFF_WG  + (size_t)3000*512;    // 1536x2080
constexpr size_t BOFF_H0   = BOFF_WIH + (size_t)1536*2080;   // 128x512
constexpr size_t BOFF_X    = BOFF_H0  + (size_t)Bn*Hd;       // 128x2080
constexpr size_t BOFF_HN   = BOFF_X   + (size_t)Bn*XD;       // 128x512
constexpr size_t BOFF_TBCP = BOFF_HN  + (size_t)Bn*Hd;       // 16384x512 tanh(copy)
constexpr size_t TOT_BF    = BOFF_TBCP+ (size_t)Bn*TBt*Hd;
__device__ __nv_bfloat16 g_bf[TOT_BF];

__device__ __forceinline__ float sigmoidf_(float x) { return 1.0f / (1.0f + expf(-x)); }

// ---------------- converts ----------------
__global__ void conv_weights_k(const float* __restrict__ aw, const float* __restrict__ wc,
                               const float* __restrict__ wg, const float* __restrict__ wih,
                               const float* __restrict__ whh, const float* __restrict__ h0,
                               __nv_bfloat16* __restrict__ bf) {
    int i = blockIdx.x * 256 + threadIdx.x;
    if (i < 262144)       { int r = i >> 9, c = i & 511; bf[BOFF_W1 + i] = __float2bfloat16(aw[(size_t)r * 1024 + c]); }
    else if (i < 524288)  { int j = i - 262144; int r = j >> 9, c = j & 511; bf[BOFF_W2 + j] = __float2bfloat16(aw[(size_t)r * 1024 + 512 + c]); }
    else if (i < 786432)  { int j = i - 524288;  bf[BOFF_WC  + j] = __float2bfloat16(wc[j]); }
    else if (i < 2322432) { int j = i - 786432;  bf[BOFF_WG  + j] = __float2bfloat16(wg[j]); }
    else if (i < 5517312) { int j = i - 2322432; bf[BOFF_WIH + j] = __float2bfloat16(wih[j]); }
    else if (i < 6303744) { int j = i - 5517312; bf[BOFF_WHH + j] = __float2bfloat16(whh[j]); }
    else if (i < 6369280) { int j = i - 6303744; bf[BOFF_H0  + j] = __float2bfloat16(h0[j]); }
}

__global__ void f2bf_k(const float* __restrict__ in, __nv_bfloat16* __restrict__ outp, int n4) {
    int i = blockIdx.x * 256 + threadIdx.x;
    if (i >= n4) return;
    float4 v = ((const float4*)in)[i];
    ((__nv_bfloat162*)outp)[2*i]   = __floats2bfloat162_rn(v.x, v.y);
    ((__nv_bfloat162*)outp)[2*i+1] = __floats2bfloat162_rn(v.z, v.w);
}

// ---------------- mma helpers ----------------
__device__ __forceinline__ uint32_t sptr(const void* p) {
    return (uint32_t)__cvta_generic_to_shared(p);
}
__device__ __forceinline__ void ldsm_x4(uint32_t& r0, uint32_t& r1, uint32_t& r2, uint32_t& r3, uint32_t a) {
    asm volatile("ldmatrix.sync.aligned.m8n8.x4.shared.b16 {%0,%1,%2,%3}, [%4];\n"
                 : "=r"(r0), "=r"(r1), "=r"(r2), "=r"(r3) : "r"(a));
}
__device__ __forceinline__ void mma_bf16(float* d, const uint32_t* a, const uint32_t* b) {
    asm volatile("mma.sync.aligned.m16n8k16.row.col.f32.bf16.bf16.f32 "
                 "{%0,%1,%2,%3},{%4,%5,%6,%7},{%8,%9},{%0,%1,%2,%3};\n"
                 : "+f"(d[0]), "+f"(d[1]), "+f"(d[2]), "+f"(d[3])
                 : "r"(a[0]), "r"(a[1]), "r"(a[2]), "r"(a[3]), "r"(b[0]), "r"(b[1]));
}
__device__ __forceinline__ void cp16(uint32_t dst, const void* src, bool pred) {
    int sz = pred ? 16 : 0;
    asm volatile("cp.async.cg.shared.global [%0], [%1], 16, %2;\n"
                 :: "r"(dst), "l"(src), "r"(sz));
}
__device__ __forceinline__ void cp_commit() { asm volatile("cp.async.commit_group;\n"); }
template<int Nw> __device__ __forceinline__ void cp_wait() {
    asm volatile("cp.async.wait_group %0;\n" :: "n"(Nw));
}

#define GPAD 40
#define SKSTG 3
constexpr int DSMEM_SK  = SKSTG * 2 * 128 * GPAD * 2;          // 61440
constexpr int DSMEM_BIG = 3 * (128 + 256) * GPAD * 2;          // 92160

__device__ __forceinline__ int bat_of(int r) {
    return (r < Bn*TU) ? (r >> 8)
         : (r < Bn*TU + Bn*TBt) ? ((r - Bn*TU) >> 7)
         : ((r - Bn*TU - Bn*TBt) >> 6);
}

// ---------------- skinny split-K GEMM (M=128 tiles) ----------------
__global__ __launch_bounds__(256) void skinny_gemm_k(
    const __nv_bfloat16* __restrict__ A, int lda,
    const __nv_bfloat16* __restrict__ Bw, int ldb,
    float* __restrict__ Cp, int M, int N, int Kc)
{
    extern __shared__ __align__(16) __nv_bfloat16 dsm[];
    __nv_bfloat16* As = dsm;
    __nv_bfloat16* Bs = dsm + (size_t)SKSTG * 128 * GPAD;
    int tid = threadIdx.x;
    int warp = tid >> 5, lane = tid & 31;
    int m0 = blockIdx.y * 128, n0 = blockIdx.x * 128;
    int koff = blockIdx.z * Kc;
    float* C = Cp + (size_t)blockIdx.z * M * N;
    int wm = (warp >> 2) * 64, wn = (warp & 3) * 32;

    float acc[4][4][4];
    #pragma unroll
    for (int i = 0; i < 4; i++)
        #pragma unroll
        for (int j = 0; j < 4; j++)
            #pragma unroll
            for (int q = 0; q < 4; q++) acc[i][j][q] = 0.f;

    int lr = tid >> 1;
    int lc0 = (tid & 1) * 16;
    auto load_stage = [&](int st, int k0) {
        __nv_bfloat16* as = As + (size_t)st * 128 * GPAD;
        __nv_bfloat16* bs = Bs + (size_t)st * 128 * GPAD;
        #pragma unroll
        for (int s = 0; s < 2; s++) {
            int c = lc0 + s * 8;
            cp16(sptr(as + lr * GPAD + c), A + (size_t)(m0 + lr) * lda + koff + k0 + c, true);
            int gn = n0 + lr;
            bool pred = gn < N;
            cp16(sptr(bs + lr * GPAD + c),
                 Bw + (size_t)(pred ? gn : (N - 1)) * ldb + koff + k0 + c, pred);
        }
        cp_commit();
    };

    int nk = Kc >> 5;
    load_stage(0, 0);
    load_stage(1, 32);
    for (int it = 0; it < nk; it++) {
        if (it == nk - 1) cp_wait<0>(); else cp_wait<1>();
        __syncthreads();
        if (it + 2 < nk) load_stage((it + 2) % SKSTG, (it + 2) * 32);
        int cur = it % SKSTG;
        __nv_bfloat16* as = As + (size_t)cur * 128 * GPAD;
        __nv_bfloat16* bs = Bs + (size_t)cur * 128 * GPAD;
        #pragma unroll
        for (int kk = 0; kk < 2; kk++) {
            int kb = kk * 16;
            uint32_t afr[4][4], bfr[4][2];
            #pragma unroll
            for (int mt = 0; mt < 4; mt++) {
                int row = wm + mt * 16 + (lane & 15);
                int col = kb + (lane >> 4) * 8;
                ldsm_x4(afr[mt][0], afr[mt][1], afr[mt][2], afr[mt][3],
                        sptr(as + row * GPAD + col));
            }
            #pragma unroll
            for (int p = 0; p < 2; p++) {
                int row = wn + p * 16 + (lane & 7) + ((lane >> 4) & 1) * 8;
                int col = kb + ((lane >> 3) & 1) * 8;
                ldsm_x4(bfr[2*p][0], bfr[2*p][1], bfr[2*p+1][0], bfr[2*p+1][1],
                        sptr(bs + row * GPAD + col));
            }
            #pragma unroll
            for (int mt = 0; mt < 4; mt++)
                #pragma unroll
                for (int nt = 0; nt < 4; nt++)
                    mma_bf16(acc[mt][nt], afr[mt], bfr[nt]);
        }
    }
    #pragma unroll
    for (int mt = 0; mt < 4; mt++) {
        int r = m0 + wm + mt * 16 + (lane >> 2);
        #pragma unroll
        for (int nt = 0; nt < 4; nt++) {
            int col = n0 + wn + nt * 8 + (lane & 3) * 2;
            if (col < N) {
                *(float2*)(C + (size_t)r * N + col)       = make_float2(acc[mt][nt][0], acc[mt][nt][1]);
                *(float2*)(C + (size_t)(r + 8) * N + col) = make_float2(acc[mt][nt][2], acc[mt][nt][3]);
            }
        }
    }
}

// ---------------- fused big GEMM (mma.sync), A read as fp32 + inline convert ----------------
// grid (2, YATT+YCPY), 512 threads, tile 128x256, K=512 in 16 chunks of 32, 3 stages.
__global__ __launch_bounds__(512) void fused_gemm_k(
    const float* __restrict__ eu, const float* __restrict__ eb, const float* __restrict__ ep,
    const __nv_bfloat16* __restrict__ bf, const float* __restrict__ wcb,
    __nv_bfloat16* __restrict__ bTB, float* __restrict__ spart,
    const float* __restrict__ up, const float* __restrict__ ab,
    const float* __restrict__ v)
{
    constexpr int K = 512;
    constexpr int N = 512;
    extern __shared__ __align__(16) __nv_bfloat16 dsm[];
    __nv_bfloat16* Asm = dsm;                                  // [3][128*GPAD]
    __nv_bfloat16* Bsm = dsm + (size_t)3 * 128 * GPAD;         // [3][256*GPAD]
    __shared__ float part[128][4];
    int tid = threadIdx.x;
    int warp = tid >> 5, lane = tid & 31;
    int by = blockIdx.y;
    bool isAtt = by < YATT;
    const float* A; int mloc;
    if (!isAtt)        { A = eb; mloc = (by - YATT) * 128; }
    else if (by < 256) { A = eu; mloc = by * 128; }
    else if (by < 384) { A = eb; mloc = (by - 256) * 128; }
    else               { A = ep; mloc = (by - 384) * 128; }
    int m0g = by * 128;   // merged-row base (valid only when isAtt)
    const __nv_bfloat16* Bw = isAtt ? (bf + BOFF_W2) : (bf + BOFF_WC);
    int n0 = blockIdx.x * 256;
    int wm = (warp >> 2) * 32, wn = (warp & 3) * 64;

    float acc[2][8][4];
    #pragma unroll
    for (int i = 0; i < 2; i++)
        #pragma unroll
        for (int j = 0; j < 8; j++)
            #pragma unroll
            for (int q = 0; q < 4; q++) acc[i][j][q] = 0.f;

    // A: fp32 gmem -> regs -> bf16 smem. thread t: row = t>>2, colgroup = t&3 (8 cols).
    int arow = tid >> 2, acg = (tid & 3) * 8;
    const float* aptr = A + (size_t)(mloc + arow) * K + acg;
    float4 ar0, ar1;
    auto ldgA = [&](int chunk) {
        const float4* p = (const float4*)(aptr + chunk * 32);
        ar0 = p[0]; ar1 = p[1];
    };
    auto stsA = [&](int st) {
        uint4 pk;
        __nv_bfloat162 t0 = __floats2bfloat162_rn(ar0.x, ar0.y);
        __nv_bfloat162 t1 = __floats2bfloat162_rn(ar0.z, ar0.w);
        __nv_bfloat162 t2 = __floats2bfloat162_rn(ar1.x, ar1.y);
        __nv_bfloat162 t3 = __floats2bfloat162_rn(ar1.z, ar1.w);
        pk.x = *(uint32_t*)&t0; pk.y = *(uint32_t*)&t1;
        pk.z = *(uint32_t*)&t2; pk.w = *(uint32_t*)&t3;
        *(uint4*)(Asm + (size_t)st * 128 * GPAD + arow * GPAD + acg) = pk;
    };
    auto loadB = [&](int st, int chunk) {
        int koff = chunk * 32;
        __nv_bfloat16* bs = Bsm + (size_t)st * 256 * GPAD;
        #pragma unroll
        for (int s = 0; s < 2; s++) {
            int j = tid + s * 512;
            int br = j >> 2, bc = (j & 3) * 8;
            cp16(sptr(bs + br * GPAD + bc), Bw + (size_t)(n0 + br) * K + koff + bc, true);
        }
        cp_commit();
    };

    // prologue
    ldgA(0); stsA(0);
    ldgA(1); stsA(1);
    loadB(0, 0); loadB(1, 1);
    ldgA(2);

    constexpr int nk = K / 32;   // 16
    for (int c = 0; c < nk; c++) {
        if (c == nk - 1) cp_wait<0>(); else cp_wait<1>();
        __syncthreads();
        if (c + 2 < nk) {
            int st = (c + 2) % 3;
            stsA(st);
            loadB(st, c + 2);
            if (c + 3 < nk) ldgA(c + 3);
        }
        int cur = c % 3;
        __nv_bfloat16* as = Asm + (size_t)cur * 128 * GPAD;
        __nv_bfloat16* bs = Bsm + (size_t)cur * 256 * GPAD;
        #pragma unroll
        for (int kk = 0; kk < 2; kk++) {
            int kb = kk * 16;
            uint32_t afr[2][4], bfr[8][2];
            #pragma unroll
            for (int mt = 0; mt < 2; mt++) {
                int row = wm + mt * 16 + (lane & 15);
                int col = kb + (lane >> 4) * 8;
                ldsm_x4(afr[mt][0], afr[mt][1], afr[mt][2], afr[mt][3],
                        sptr(as + row * GPAD + col));
            }
            #pragma unroll
            for (int p = 0; p < 4; p++) {
                int row = wn + p * 16 + (lane & 7) + ((lane >> 4) & 1) * 8;
                int col = kb + ((lane >> 3) & 1) * 8;
                ldsm_x4(bfr[2*p][0], bfr[2*p][1], bfr[2*p+1][0], bfr[2*p+1][1],
                        sptr(bs + row * GPAD + col));
            }
            #pragma unroll
            for (int mt = 0; mt < 2; mt++)
                #pragma unroll
                for (int nt = 0; nt < 8; nt++)
                    mma_bf16(acc[mt][nt], afr[mt], bfr[nt]);
        }
    }

    if (!isAtt) {
        // tanh epilogue -> bf16 bTB (row = copy-token index)
        #pragma unroll
        for (int mt = 0; mt < 2; mt++) {
            int r = mloc + wm + mt * 16 + (lane >> 2);
            #pragma unroll
            for (int nt = 0; nt < 8; nt++) {
                int col = n0 + wn + nt * 8 + (lane & 3) * 2;
                float b0 = wcb[col], b1 = wcb[col + 1];
                *(__nv_bfloat162*)(bTB + (size_t)r * N + col) =
                    __floats2bfloat162_rn(tanhf(acc[mt][nt][0] + b0), tanhf(acc[mt][nt][1] + b1));
                *(__nv_bfloat162*)(bTB + (size_t)(r + 8) * N + col) =
                    __floats2bfloat162_rn(tanhf(acc[mt][nt][2] + b0), tanhf(acc[mt][nt][3] + b1));
            }
        }
    } else {
        // score epilogue
        #pragma unroll
        for (int mt = 0; mt < 2; mt++) {
            int r0 = wm + mt * 16 + (lane >> 2);
            int r1 = r0 + 8;
            const float* u0 = up + (size_t)bat_of(m0g + r0) * 2048;
            const float* u1 = up + (size_t)bat_of(m0g + r1) * 2048;
            float ls0 = 0.f, ls1 = 0.f;
            #pragma unroll
            for (int nt = 0; nt < 8; nt++) {
                int col = n0 + wn + nt * 8 + (lane & 3) * 2;
                #pragma unroll
                for (int q = 0; q < 2; q++) {
                    int cI = col + q;
                    float uv0 = u0[cI] + u0[USLAB + cI] + u0[2*USLAB + cI] + u0[3*USLAB + cI] + ab[cI];
                    float uv1 = u1[cI] + u1[USLAB + cI] + u1[2*USLAB + cI] + u1[3*USLAB + cI] + ab[cI];
                    float vv = v[cI];
                    ls0 += vv * tanhf(acc[mt][nt][q]     + uv0);
                    ls1 += vv * tanhf(acc[mt][nt][2 + q] + uv1);
                }
            }
            #pragma unroll
            for (int s = 1; s < 4; s <<= 1) {
                ls0 += __shfl_xor_sync(0xffffffffu, ls0, s);
                ls1 += __shfl_xor_sync(0xffffffffu, ls1, s);
            }
            if ((lane & 3) == 0) {
                part[r0][warp & 3] = ls0;
                part[r1][warp & 3] = ls1;
            }
        }
        __syncthreads();
        if (tid < 128) {
            float tot = part[tid][0] + part[tid][1] + part[tid][2] + part[tid][3];
            spart[(size_t)(m0g + tid) * 2 + blockIdx.x] = tot;
        }
    }
}

// ---------------- merged softmax + ctx (fp32 enc) ----------------
__global__ void softmax_ctx_all_k(const float* __restrict__ sp,
                                  const int* __restrict__ ids_u, const int* __restrict__ ids_b,
                                  const int* __restrict__ ids_p,
                                  const float* __restrict__ eu, const float* __restrict__ eb,
                                  const float* __restrict__ ep, float* __restrict__ x) {
    int b = blockIdx.x, chunk = blockIdx.y, seg = blockIdx.z, tid = threadIdx.x;
    int T; const int* ids; const float* enc; int tokbase;
    if (seg == 0)      { T = TU;  ids = ids_u; enc = eu; tokbase = 0; }
    else if (seg == 1) { T = TBt; ids = ids_b; enc = eb; tokbase = Bn*TU; }
    else               { T = TPt; ids = ids_p; enc = ep; tokbase = Bn*TU + Bn*TBt; }
    __shared__ float sw[256];
    __shared__ float red[256];
    float sv = -3.0e38f;
    if (tid < T) {
        const float* s2 = sp + (size_t)(tokbase + b * T + tid) * 2;
        sv = s2[0] + s2[1];
        if (ids[(size_t)b * T + tid] == 0) sv = NEGV;
    }
    red[tid] = sv; __syncthreads();
    for (int s = 128; s; s >>= 1) { if (tid < s) red[tid] = fmaxf(red[tid], red[tid + s]); __syncthreads(); }
    float m = red[0]; __syncthreads();
    float e = (tid < T) ? expf(sv - m) : 0.f;
    red[tid] = e; __syncthreads();
    for (int s = 128; s; s >>= 1) { if (tid < s) red[tid] += red[tid + s]; __syncthreads(); }
    float Z = red[0]; __syncthreads();
    sw[tid] = e / Z; __syncthreads();
    int h = chunk * 256 + tid;
    float acc = 0.f;
    const float* epp = enc + (size_t)b * T * Hd + h;
    #pragma unroll 4
    for (int t = 0; t < T; t++) acc += sw[t] * epp[(size_t)t * Hd];
    x[(size_t)b * XD + Ed + seg * Hd + h] = acc;
}

// ---------------- x: emb + db slots ----------------
__global__ void fill_x_k(const int* __restrict__ w, const float* __restrict__ emb_table,
                         const float* __restrict__ db, float* __restrict__ x) {
    int b = blockIdx.x, tid = threadIdx.x;
    int wid = w[b];
    for (int i = tid; i < Ed; i += 256) x[(size_t)b * XD + i] = emb_table[(size_t)wid * Ed + i];
    for (int i = tid; i < PTRd; i += 256) x[(size_t)b * XD + Ed + 3 * Hd + i] = db[(size_t)b * PTRd + i];
}

// ---------------- GRU cell ----------------
__global__ void gru_cell_k(const float* __restrict__ gip, const float* __restrict__ ughp,
                           const float* __restrict__ bih, const float* __restrict__ bhh,
                           const float* __restrict__ h0, float* __restrict__ hnew,
                           __nv_bfloat16* __restrict__ hnbf) {
    int i = blockIdx.x * 256 + threadIdx.x;
    if (i >= Bn * Hd) return;
    int b = i / Hd, j = i % Hd;
    float gi[3], gh[3];
    #pragma unroll
    for (int g = 0; g < 3; g++) {
        int col = g * Hd + j;
        float s = bih[col];
        #pragma unroll
        for (int z = 0; z < 5; z++) s += gip[(size_t)z * Bn * G3H + (size_t)b * G3H + col];
        gi[g] = s;
        float t = bhh[col];
        #pragma unroll
        for (int z = 0; z < 4; z++) t += ughp[(size_t)z * USLAB + (size_t)b * 2048 + 512 + col];
        gh[g] = t;
    }
    float r = sigmoidf_(gi[0] + gh[0]);
    float z = sigmoidf_(gi[1] + gh[1]);
    float n = tanhf(gi[2] + r * gh[2]);
    float hv = (1.f - z) * n + z * h0[i];
    hnew[i] = hv;
    hnbf[i] = __float2bfloat16(hv);
}

// ---------------- cp_raw ----------------
__global__ void cpraw_k(const __nv_bfloat16* __restrict__ TB, const float* __restrict__ hnew,
                        const int* __restrict__ ids, float* __restrict__ cpr) {
    int tok = blockIdx.x * 8 + (threadIdx.x >> 5);
    int lane = threadIdx.x & 31;
    int b = tok / TBt;
    const __nv_bfloat162* e2 = (const __nv_bfloat162*)(TB + (size_t)tok * Hd);
    const float2* hn2 = (const float2*)(hnew + (size_t)b * Hd);
    float acc = 0.f;
    #pragma unroll 4
    for (int j = lane; j < Hd / 2; j += 32) {
        __nv_bfloat162 p = e2[j];
        float2 h2 = hn2[j];
        acc += h2.x * __bfloat162float(p.x) + h2.y * __bfloat162float(p.y);
    }
    #pragma unroll
    for (int s = 16; s; s >>= 1) acc += __shfl_down_sync(0xffffffffu, acc, s);
    if (lane == 0) cpr[tok] = (ids[tok] == 0) ? NEGV : acc;
}

// ---------------- final epilogue ----------------
__global__ void final_k(const float* __restrict__ genp, const float* __restrict__ genb,
                        const float* __restrict__ cpr, const int* __restrict__ nounk,
                        float* __restrict__ out) {
    int b = blockIdx.x, tid = threadIdx.x;
    __shared__ float Lg[Vd];
    __shared__ float Lc[Vd + TBt];
    __shared__ float addv[VOOVd - Vd];
    __shared__ float red[256];
    for (int n = tid; n < Vd; n += 256) {
        float s = genb[n];
        #pragma unroll
        for (int z = 0; z < 4; z++) s += genp[(size_t)z * Bn * Vd + (size_t)b * Vd + n];
        Lg[n] = s;
    }
    for (int n = tid; n < Vd + TBt; n += 256) Lc[n] = 0.f;
    for (int n = tid; n < VOOVd - Vd; n += 256) addv[n] = 0.f;
    __syncthreads();
    if (tid == 0) {
        for (int t = 0; t < TBt; t++) {
            int nk = nounk[(size_t)b * TBt + t];
            int col = (nk < Vd) ? nk : (Vd + t);
            Lc[col] += cpr[(size_t)b * TBt + t];
        }
    }
    __syncthreads();
    float lm = -3.0e38f;
    for (int n = tid; n < 2 * Vd + TBt; n += 256) {
        float v = (n < Vd) ? Lg[n] : Lc[n - Vd];
        lm = fmaxf(lm, v);
    }
    red[tid] = lm; __syncthreads();
    for (int s = 128; s; s >>= 1) { if (tid < s) red[tid] = fmaxf(red[tid], red[tid + s]); __syncthreads(); }
    float M = red[0]; __syncthreads();
    float ls = 0.f;
    for (int n = tid; n < 2 * Vd + TBt; n += 256) {
        float v = (n < Vd) ? Lg[n] : Lc[n - Vd];
        ls += expf(v - M);
    }
    red[tid] = ls; __syncthreads();
    for (int s = 128; s; s >>= 1) { if (tid < s) red[tid] += red[tid + s]; __syncthreads(); }
    float logZ = M + logf(red[0]); __syncthreads();
    if (tid == 0) {
        for (int t = 0; t < TBt; t++) {
            int nk = nounk[(size_t)b * TBt + t];
            if (nk >= Vd) addv[nk - Vd] += expf(Lc[Vd + t] - logZ);
        }
    }
    __syncthreads();
    for (int n = tid; n < VOOVd; n += 256) {
        float val;
        if (n < Vd) {
            float a = Lg[n] - logZ;
            float c = Lc[n] - logZ;
            float mm = fmaxf(a, c);
            val = mm + log1pf(expf(-fabsf(a - c)));
        } else {
            float v = addv[n - Vd];
            val = (v > 0.f) ? logf(fmaxf(v, 1e-38f)) : NEGV;
        }
        out[(size_t)b * VOOVd + n] = val;
    }
}

// ---------------- host ----------------
static inline int cdiv(int a, int b) { return (a + b - 1) / b; }

extern "C" void kernel_launch(void* const* d_in, const int* in_sizes, int n_in,
                              void* d_out, int out_size) {
    const int*   dec_last_w = (const int*)  d_in[0];
    const float* h0         = (const float*)d_in[1];
    const float* usdx_h     = (const float*)d_in[2];
    const float* bspn_h     = (const float*)d_in[3];
    const float* pv_h       = (const float*)d_in[4];
    const float* db         = (const float*)d_in[5];
    const int*   usdx_ids   = (const int*)  d_in[6];
    const int*   bspn_ids   = (const int*)  d_in[7];
    const int*   pv_ids     = (const int*)  d_in[8];
    const int*   nounk      = (const int*)  d_in[9];
    // d_in[10] = bspn_onehot: unused
    const float* emb        = (const float*)d_in[11];
    const float* attn_W     = (const float*)d_in[12];
    const float* attn_b     = (const float*)d_in[13];
    const float* v_w        = (const float*)d_in[14];
    const float* Wc         = (const float*)d_in[15];
    const float* Wcb        = (const float*)d_in[16];
    const float* Wg         = (const float*)d_in[17];
    const float* Wgb        = (const float*)d_in[18];
    const float* Wih        = (const float*)d_in[19];
    const float* Whh        = (const float*)d_in[20];
    const float* bih        = (const float*)d_in[21];
    const float* bhh        = (const float*)d_in[22];
    float* out = (float*)d_out;

    float* S = nullptr;  cudaGetSymbolAddress((void**)&S, g_scratch);
    __nv_bfloat16* Bf = nullptr;  cudaGetSymbolAddress((void**)&Bf, g_bf);

    float* UGHP = S + OFF_UGHP;
    float* GIP  = S + OFF_GIP;
    float* GENP = S + OFF_GENP;
    float* SP   = S + OFF_SP;
    float* X    = S + OFF_X;
    float* HNEW = S + OFF_HNEW;
    float* CPR  = S + OFF_CPR;

    __nv_bfloat16* bW1c = Bf + BOFF_W1;
    __nv_bfloat16* bWG  = Bf + BOFF_WG;
    __nv_bfloat16* bWIH = Bf + BOFF_WIH;
    __nv_bfloat16* bH0  = Bf + BOFF_H0;
    __nv_bfloat16* bX   = Bf + BOFF_X;
    __nv_bfloat16* bHN  = Bf + BOFF_HN;
    __nv_bfloat16* bTB  = Bf + BOFF_TBCP;

    static bool attr_set = false;
    if (!attr_set) {
        cudaFuncSetAttribute(skinny_gemm_k, cudaFuncAttributeMaxDynamicSharedMemorySize, DSMEM_SK);
        cudaFuncSetAttribute(fused_gemm_k, cudaFuncAttributeMaxDynamicSharedMemorySize, DSMEM_BIG);
        attr_set = true;
    }

    // 0: weight converts
    conv_weights_k<<<cdiv(6369280, 256), 256>>>(attn_W, Wc, Wg, Wih, Whh, h0, Bf);
    // 1: UGH partials, splitK=4
    skinny_gemm_k<<<dim3(16, 1, 4), 256, DSMEM_SK>>>(bH0, 512, bW1c, 512, UGHP, Bn, 2048, 128);
    // 2: emb + db (input-only, placed here so fused GEMM is in the profiled slot)
    fill_x_k<<<Bn, 256>>>(dec_last_w, emb, db, X);
    // 3 (profiled slot): fused attention-score + copy-tanh GEMM, fp32-A inline convert
    fused_gemm_k<<<dim3(2, YATT + YCPY), 512, DSMEM_BIG>>>(usdx_h, bspn_h, pv_h, Bf, Wcb, bTB, SP, UGHP, attn_b, v_w);
    // 4: softmax + ctx (fp32 enc)
    softmax_ctx_all_k<<<dim3(Bn, 2, 3), 256>>>(SP, usdx_ids, bspn_ids, pv_ids, usdx_h, bspn_h, pv_h, X);
    // 5: X -> bf16
    f2bf_k<<<cdiv(Bn*XD/4, 256), 256>>>(X, bX, Bn*XD/4);
    // 6: GI partials, splitK=5, Kc=416
    skinny_gemm_k<<<dim3(12, 1, 5), 256, DSMEM_SK>>>(bX, XD, bWIH, XD, GIP, Bn, G3H, 416);
    // 7: GRU cell
    gru_cell_k<<<cdiv(Bn*Hd, 256), 256>>>(GIP, UGHP, bih, bhh, h0, HNEW, bHN);
    // 8: GEN partials, splitK=4
    skinny_gemm_k<<<dim3(cdiv(3000, 128), 1, 4), 256, DSMEM_SK>>>(bHN, 512, bWG, 512, GENP, Bn, Vd, 128);
    // 9: copy scores
    cpraw_k<<<(Bn*TBt)/8, 256>>>(bTB, HNEW, bspn_ids, CPR);
    // 10: final epilogue
    final_k<<<Bn, 256>>>(GENP, Wgb, CPR, nounk, out);
}